// round 6
// baseline (speedup 1.0000x reference)
#include <cuda_runtime.h>
#include <math.h>

#define D_MODEL 1024
#define NHEAD   16
#define DK      64
#define BATCH   2
#define SEQ     2048
#define M_TOT   (BATCH*SEQ)   // 4096

// Scratch (allocation-free rule: __device__ globals)
__device__ float g_Q [BATCH*NHEAD*SEQ*DK];   // [B,H,S,DK] 16 MB
__device__ float g_K [BATCH*NHEAD*SEQ*DK];
__device__ float g_V [BATCH*NHEAD*SEQ*DK];
__device__ float g_AO[BATCH*SEQ*D_MODEL];    // merged attention output [B,S,D]

// ---------------------------------------------------------------------------
// GEMM: C = A[M,1024] @ W[1024,1024]^T + bias   (A, W row-major; K-contiguous)
// MODE 0: C row-major [M,1024]
// MODE 1: head-split write: m=b*S+s, n=h*64+dk -> C[((b*H+h)*S+s)*64+dk]
// 128x128 block tile, K-tile 16, 256 threads, 8x8 micro-tile per thread.
// ---------------------------------------------------------------------------
template<int MODE>
__global__ void __launch_bounds__(256) gemm_bias_kernel(
    const float* __restrict__ A, const float* __restrict__ W,
    const float* __restrict__ bias, float* __restrict__ C)
{
    constexpr int K  = 1024;
    constexpr int TK = 16;
    __shared__ float As[TK][132];   // [k][m], padded
    __shared__ float Bs[TK][132];   // [k][n], padded

    const int tid = threadIdx.x;
    const int tn  = tid & 15;       // 0..15 -> n micro
    const int tm  = tid >> 4;       // 0..15 -> m micro
    const int m0  = blockIdx.y * 128;
    const int n0  = blockIdx.x * 128;

    float acc[8][8];
#pragma unroll
    for (int i = 0; i < 8; i++)
#pragma unroll
        for (int j = 0; j < 8; j++) acc[i][j] = 0.f;

    for (int k0 = 0; k0 < K; k0 += TK) {
        // Cooperative loads: 128x16 tile each = 512 float4; 2 per thread.
#pragma unroll
        for (int t = 0; t < 2; t++) {
            int f   = tid + t * 256;     // 0..511
            int row = f >> 2;            // 0..127
            int c4  = (f & 3) * 4;       // 0,4,8,12 within k-tile
            float4 va = *(const float4*)(A + (size_t)(m0 + row) * K + k0 + c4);
            As[c4 + 0][row] = va.x; As[c4 + 1][row] = va.y;
            As[c4 + 2][row] = va.z; As[c4 + 3][row] = va.w;
            float4 vb = *(const float4*)(W + (size_t)(n0 + row) * K + k0 + c4);
            Bs[c4 + 0][row] = vb.x; Bs[c4 + 1][row] = vb.y;
            Bs[c4 + 2][row] = vb.z; Bs[c4 + 3][row] = vb.w;
        }
        __syncthreads();

#pragma unroll
        for (int kk = 0; kk < TK; kk++) {
            float a[8], b[8];
            float4 t0 = *(const float4*)&As[kk][tm * 8];
            float4 t1 = *(const float4*)&As[kk][tm * 8 + 4];
            a[0]=t0.x; a[1]=t0.y; a[2]=t0.z; a[3]=t0.w;
            a[4]=t1.x; a[5]=t1.y; a[6]=t1.z; a[7]=t1.w;
            float4 u0 = *(const float4*)&Bs[kk][tn * 8];
            float4 u1 = *(const float4*)&Bs[kk][tn * 8 + 4];
            b[0]=u0.x; b[1]=u0.y; b[2]=u0.z; b[3]=u0.w;
            b[4]=u1.x; b[5]=u1.y; b[6]=u1.z; b[7]=u1.w;
#pragma unroll
            for (int i = 0; i < 8; i++)
#pragma unroll
                for (int j = 0; j < 8; j++)
                    acc[i][j] = fmaf(a[i], b[j], acc[i][j]);
        }
        __syncthreads();
    }

    // Epilogue
    const int nbase = n0 + tn * 8;
    float bs[8];
#pragma unroll
    for (int j = 0; j < 8; j++) bs[j] = bias[nbase + j];

#pragma unroll
    for (int i = 0; i < 8; i++) {
        const int m = m0 + tm * 8 + i;
        float4 r0, r1;
        r0.x = acc[i][0] + bs[0]; r0.y = acc[i][1] + bs[1];
        r0.z = acc[i][2] + bs[2]; r0.w = acc[i][3] + bs[3];
        r1.x = acc[i][4] + bs[4]; r1.y = acc[i][5] + bs[5];
        r1.z = acc[i][6] + bs[6]; r1.w = acc[i][7] + bs[7];
        if (MODE == 0) {
            float* dst = C + (size_t)m * D_MODEL + nbase;
            *(float4*)(dst)     = r0;
            *(float4*)(dst + 4) = r1;
        } else {
            const int b  = m >> 11;        // /SEQ
            const int s  = m & (SEQ - 1);
            const int h  = nbase >> 6;     // /DK
            const int dk = nbase & (DK - 1);
            float* dst = C + (((size_t)(b * NHEAD + h) * SEQ + s) * DK + dk);
            *(float4*)(dst)     = r0;
            *(float4*)(dst + 4) = r1;
        }
    }
}

// ---------------------------------------------------------------------------
// Flash attention (fp32). One block = 128 q-rows of one (b,h).
// 256 threads: pair (2 threads) per q-row; each thread owns 32 of 64 dims.
// K/V staged in smem in 32-row tiles; online softmax; pair-sum via shfl.
// ---------------------------------------------------------------------------
__global__ void __launch_bounds__(256) attn_kernel(
    const int* __restrict__ mask, float* __restrict__ AO)
{
    __shared__ float Ks[32 * DK];
    __shared__ float Vs[32 * DK];

    const int tid  = threadIdx.x;
    const int r    = tid >> 1;      // 0..127 q-row within block
    const int half = tid & 1;       // which 32-dim half
    const int bh   = blockIdx.y;    // b*H + h
    const int b    = bh >> 4;
    const int h    = bh & 15;
    const int qrow = blockIdx.x * 128 + r;

    const float* Qp = g_Q + ((size_t)bh * SEQ + qrow) * DK + half * 32;
    float q[32];
#pragma unroll
    for (int i = 0; i < 8; i++) {
        float4 v = *(const float4*)(Qp + i * 4);
        q[i*4+0]=v.x; q[i*4+1]=v.y; q[i*4+2]=v.z; q[i*4+3]=v.w;
    }

    float o[32];
#pragma unroll
    for (int i = 0; i < 32; i++) o[i] = 0.f;
    float m_run = -INFINITY, l_run = 0.f;

    const float* Kbase = g_K + (size_t)bh * SEQ * DK;
    const float* Vbase = g_V + (size_t)bh * SEQ * DK;
    const int*   mrow  = mask + ((size_t)b * SEQ + qrow) * SEQ;

    for (int kt = 0; kt < SEQ; kt += 32) {
        // Load 32x64 K and V tiles (2048 floats each): 2 float4 per thread each.
#pragma unroll
        for (int t = 0; t < 2; t++) {
            int f = tid + t * 256;   // float4 index 0..511
            *(float4*)(Ks + f * 4) = *(const float4*)(Kbase + (size_t)kt * DK + f * 4);
            *(float4*)(Vs + f * 4) = *(const float4*)(Vbase + (size_t)kt * DK + f * 4);
        }
        __syncthreads();

        float s[32];
#pragma unroll
        for (int j = 0; j < 32; j++) {
            const float* kr = Ks + j * DK + half * 32;
            float acc = 0.f;
#pragma unroll
            for (int d = 0; d < 8; d++) {
                float4 kk = *(const float4*)(kr + d * 4);
                acc = fmaf(q[d*4+0], kk.x, acc);
                acc = fmaf(q[d*4+1], kk.y, acc);
                acc = fmaf(q[d*4+2], kk.z, acc);
                acc = fmaf(q[d*4+3], kk.w, acc);
            }
            acc += __shfl_xor_sync(0xffffffffu, acc, 1);   // combine halves
            int mv = mrow[kt + j];
            s[j] = (mv == 0) ? -INFINITY : acc * 0.125f;   // 1/sqrt(64)
        }

        float mx = m_run;
#pragma unroll
        for (int j = 0; j < 32; j++) mx = fmaxf(mx, s[j]);
        const float alpha = __expf(m_run - mx);
        float psum = 0.f;
#pragma unroll
        for (int j = 0; j < 32; j++) { s[j] = __expf(s[j] - mx); psum += s[j]; }
        l_run = l_run * alpha + psum;
        m_run = mx;

#pragma unroll
        for (int i = 0; i < 32; i++) o[i] *= alpha;
#pragma unroll
        for (int j = 0; j < 32; j++) {
            const float pj = s[j];
            const float* vr = Vs + j * DK + half * 32;
#pragma unroll
            for (int d = 0; d < 8; d++) {
                float4 vv = *(const float4*)(vr + d * 4);
                o[d*4+0] = fmaf(pj, vv.x, o[d*4+0]);
                o[d*4+1] = fmaf(pj, vv.y, o[d*4+1]);
                o[d*4+2] = fmaf(pj, vv.z, o[d*4+2]);
                o[d*4+3] = fmaf(pj, vv.w, o[d*4+3]);
            }
        }
        __syncthreads();
    }

    const float inv = 1.f / l_run;
    float* dst = AO + ((size_t)b * SEQ + qrow) * D_MODEL + h * DK + half * 32;
#pragma unroll
    for (int i = 0; i < 8; i++) {
        float4 v;
        v.x = o[i*4+0] * inv; v.y = o[i*4+1] * inv;
        v.z = o[i*4+2] * inv; v.w = o[i*4+3] * inv;
        *(float4*)(dst + i * 4) = v;
    }
}

// ---------------------------------------------------------------------------
extern "C" void kernel_launch(void* const* d_in, const int* in_sizes, int n_in,
                              void* d_out, int out_size)
{
    const float* q   = (const float*)d_in[0];
    const float* k   = (const float*)d_in[1];
    const float* v   = (const float*)d_in[2];
    const int*   msk = (const int*)  d_in[3];
    const float* w_q = (const float*)d_in[4];
    const float* b_q = (const float*)d_in[5];
    const float* w_k = (const float*)d_in[6];
    const float* b_k = (const float*)d_in[7];
    const float* w_v = (const float*)d_in[8];
    const float* b_v = (const float*)d_in[9];
    const float* w_o = (const float*)d_in[10];
    const float* b_o = (const float*)d_in[11];
    float* out = (float*)d_out;

    float *gQ, *gK, *gV, *gAO;
    cudaGetSymbolAddress((void**)&gQ,  g_Q);
    cudaGetSymbolAddress((void**)&gK,  g_K);
    cudaGetSymbolAddress((void**)&gV,  g_V);
    cudaGetSymbolAddress((void**)&gAO, g_AO);

    dim3 ggrid(D_MODEL / 128, M_TOT / 128);   // (8, 32)
    gemm_bias_kernel<1><<<ggrid, 256>>>(q, w_q, b_q, gQ);
    gemm_bias_kernel<1><<<ggrid, 256>>>(k, w_k, b_k, gK);
    gemm_bias_kernel<1><<<ggrid, 256>>>(v, w_v, b_v, gV);

    dim3 agrid(SEQ / 128, BATCH * NHEAD);     // (16, 32)
    attn_kernel<<<agrid, 256>>>(msk, gAO);

    gemm_bias_kernel<0><<<ggrid, 256>>>(gAO, w_o, b_o, out);
}

// round 8
// speedup vs baseline: 2.9155x; 2.9155x over previous
#include <cuda_runtime.h>
#include <math.h>
#include <stdint.h>

#define D_MODEL 1024
#define NHEAD   16
#define DK      64
#define BATCH   2
#define SEQ     2048
#define M_TOT   (BATCH*SEQ)   // 4096

// Scratch (allocation-free rule: __device__ globals)
__device__ float g_Q [BATCH*NHEAD*SEQ*DK];   // [B,H,S,DK]
__device__ float g_K [BATCH*NHEAD*SEQ*DK];
__device__ float g_V [BATCH*NHEAD*SEQ*DK];
__device__ float g_AO[BATCH*SEQ*D_MODEL];    // merged attention output [B,S,D]

// ---------------------------------------------------------------------------
// Helpers
// ---------------------------------------------------------------------------
__device__ __forceinline__ float tf32r(float x) {
    uint32_t r;
    asm("cvt.rna.tf32.f32 %0, %1;" : "=r"(r) : "f"(x));
    return __uint_as_float(r);
}

// mma.sync m16n8k8 tf32 (sm_80+ baseline PTX -> HMMA; works on plain sm_103)
__device__ __forceinline__ void mma_tf32(float* d, const uint32_t* a, const uint32_t* b) {
    asm volatile(
        "mma.sync.aligned.m16n8k8.row.col.f32.tf32.tf32.f32 "
        "{%0,%1,%2,%3}, {%4,%5,%6,%7}, {%8,%9}, {%0,%1,%2,%3};"
        : "+f"(d[0]), "+f"(d[1]), "+f"(d[2]), "+f"(d[3])
        : "r"(a[0]), "r"(a[1]), "r"(a[2]), "r"(a[3]), "r"(b[0]), "r"(b[1]));
}

// ---------------------------------------------------------------------------
// GEMM (FFMA, proven in R5): C = A[M,1024] @ W[1024,1024]^T + bias
// MODE 0: C row-major [M,1024]
// MODE 1: head-split write into [B,H,S,64]
// ---------------------------------------------------------------------------
template<int MODE>
__global__ void __launch_bounds__(256) gemm_bias_kernel(
    const float* __restrict__ A, const float* __restrict__ W,
    const float* __restrict__ bias, float* __restrict__ C)
{
    constexpr int K  = 1024;
    constexpr int TK = 16;
    __shared__ float As[TK][132];
    __shared__ float Bs[TK][132];

    const int tid = threadIdx.x;
    const int tn  = tid & 15;
    const int tm  = tid >> 4;
    const int m0  = blockIdx.y * 128;
    const int n0  = blockIdx.x * 128;

    float acc[8][8];
#pragma unroll
    for (int i = 0; i < 8; i++)
#pragma unroll
        for (int j = 0; j < 8; j++) acc[i][j] = 0.f;

    for (int k0 = 0; k0 < K; k0 += TK) {
#pragma unroll
        for (int t = 0; t < 2; t++) {
            int f   = tid + t * 256;
            int row = f >> 2;
            int c4  = (f & 3) * 4;
            float4 va = *(const float4*)(A + (size_t)(m0 + row) * K + k0 + c4);
            As[c4 + 0][row] = va.x; As[c4 + 1][row] = va.y;
            As[c4 + 2][row] = va.z; As[c4 + 3][row] = va.w;
            float4 vb = *(const float4*)(W + (size_t)(n0 + row) * K + k0 + c4);
            Bs[c4 + 0][row] = vb.x; Bs[c4 + 1][row] = vb.y;
            Bs[c4 + 2][row] = vb.z; Bs[c4 + 3][row] = vb.w;
        }
        __syncthreads();

#pragma unroll
        for (int kk = 0; kk < TK; kk++) {
            float a[8], b[8];
            float4 t0 = *(const float4*)&As[kk][tm * 8];
            float4 t1 = *(const float4*)&As[kk][tm * 8 + 4];
            a[0]=t0.x; a[1]=t0.y; a[2]=t0.z; a[3]=t0.w;
            a[4]=t1.x; a[5]=t1.y; a[6]=t1.z; a[7]=t1.w;
            float4 u0 = *(const float4*)&Bs[kk][tn * 8];
            float4 u1 = *(const float4*)&Bs[kk][tn * 8 + 4];
            b[0]=u0.x; b[1]=u0.y; b[2]=u0.z; b[3]=u0.w;
            b[4]=u1.x; b[5]=u1.y; b[6]=u1.z; b[7]=u1.w;
#pragma unroll
            for (int i = 0; i < 8; i++)
#pragma unroll
                for (int j = 0; j < 8; j++)
                    acc[i][j] = fmaf(a[i], b[j], acc[i][j]);
        }
        __syncthreads();
    }

    const int nbase = n0 + tn * 8;
    float bs[8];
#pragma unroll
    for (int j = 0; j < 8; j++) bs[j] = bias[nbase + j];

#pragma unroll
    for (int i = 0; i < 8; i++) {
        const int m = m0 + tm * 8 + i;
        float4 r0, r1;
        r0.x = acc[i][0] + bs[0]; r0.y = acc[i][1] + bs[1];
        r0.z = acc[i][2] + bs[2]; r0.w = acc[i][3] + bs[3];
        r1.x = acc[i][4] + bs[4]; r1.y = acc[i][5] + bs[5];
        r1.z = acc[i][6] + bs[6]; r1.w = acc[i][7] + bs[7];
        if (MODE == 0) {
            float* dst = C + (size_t)m * D_MODEL + nbase;
            *(float4*)(dst)     = r0;
            *(float4*)(dst + 4) = r1;
        } else {
            const int b  = m >> 11;
            const int s  = m & (SEQ - 1);
            const int h  = nbase >> 6;
            const int dk = nbase & (DK - 1);
            float* dst = C + (((size_t)(b * NHEAD + h) * SEQ + s) * DK + dk);
            *(float4*)(dst)     = r0;
            *(float4*)(dst + 4) = r1;
        }
    }
}

// ---------------------------------------------------------------------------
// Flash attention with mma.sync tf32 (m16n8k8).
// CTA: 128 q-rows x one (b,h). 8 warps; warp w owns q-rows [w*16, w*16+16).
// Key tile = 64. Q[128x64], K[64x64], V[64x64], P[128x64] in smem.
// Pads: A-frag/K-B-frag pattern conflict-free with pad%32==4 (68);
//       V-B-frag pattern conflict-free with pad%32==8 (72).
// ---------------------------------------------------------------------------
#define QPAD 68
#define KPAD 68
#define VPAD 72
#define PPAD 68
#define ATTN_SMEM ((128*QPAD + 64*KPAD + 64*VPAD + 128*PPAD) * 4)

__global__ void __launch_bounds__(256) attn_kernel(
    const int* __restrict__ mask, float* __restrict__ AO)
{
    extern __shared__ float sf[];
    float* Qs = sf;                       // [128][QPAD] row-major [q][d]
    float* Ks = Qs + 128 * QPAD;          // [64][KPAD]  [key][d]
    float* Vs = Ks + 64 * KPAD;           // [64][VPAD]  [key][d]
    float* Ps = Vs + 64 * VPAD;           // [128][PPAD] [q][key]

    const int tid  = threadIdx.x;
    const int w    = tid >> 5;
    const int lane = tid & 31;
    const int quad = lane >> 2;   // 0..7
    const int qt   = lane & 3;    // 0..3
    const int bh   = blockIdx.y;
    const int b    = bh >> 4;
    const int h    = bh & 15;
    const int q0   = blockIdx.x * 128;
    const int r0   = w * 16 + quad;       // base q-row (local) of this thread

    const float* Qg = g_Q + ((size_t)bh * SEQ + q0) * DK;
    const float* Kg = g_K + (size_t)bh * SEQ * DK;
    const float* Vg = g_V + (size_t)bh * SEQ * DK;
    const int*   Mb = mask + (size_t)b * SEQ * SEQ;

    // Load Q tile once (tf32-rounded)
#pragma unroll
    for (int t = 0; t < 8; t++) {
        int f  = tid + t * 256;           // 0..2047
        int m  = f >> 4;
        int c4 = (f & 15) * 4;
        float4 v = *(const float4*)(Qg + (size_t)m * DK + c4);
        v.x = tf32r(v.x); v.y = tf32r(v.y); v.z = tf32r(v.z); v.w = tf32r(v.w);
        *(float4*)(Qs + m * QPAD + c4) = v;
    }

    float oacc[8][4];
#pragma unroll
    for (int nf = 0; nf < 8; nf++)
#pragma unroll
        for (int j = 0; j < 4; j++) oacc[nf][j] = 0.f;
    float mi[2] = {-INFINITY, -INFINITY};
    float li[2] = {0.f, 0.f};

    for (int kt = 0; kt < SEQ; kt += 64) {
        // Load K and V tiles (tf32-rounded)
#pragma unroll
        for (int t = 0; t < 4; t++) {
            int f   = tid + t * 256;      // 0..1023
            int key = f >> 4;
            int c4  = (f & 15) * 4;
            float4 kv = *(const float4*)(Kg + (size_t)(kt + key) * DK + c4);
            kv.x = tf32r(kv.x); kv.y = tf32r(kv.y); kv.z = tf32r(kv.z); kv.w = tf32r(kv.w);
            *(float4*)(Ks + key * KPAD + c4) = kv;
            float4 vv = *(const float4*)(Vg + (size_t)(kt + key) * DK + c4);
            vv.x = tf32r(vv.x); vv.y = tf32r(vv.y); vv.z = tf32r(vv.z); vv.w = tf32r(vv.w);
            *(float4*)(Vs + key * VPAD + c4) = vv;
        }
        __syncthreads();

        // ---- QK^T: S[16q x 64k] per warp ----
        float sacc[8][4];
#pragma unroll
        for (int nf = 0; nf < 8; nf++)
#pragma unroll
            for (int j = 0; j < 4; j++) sacc[nf][j] = 0.f;

        const uint32_t* Qu = (const uint32_t*)Qs;
        const uint32_t* Ku = (const uint32_t*)Ks;
#pragma unroll
        for (int kd = 0; kd < 8; kd++) {
            uint32_t a[4];
            const uint32_t* ap = Qu + r0 * QPAD + kd * 8 + qt;
            a[0] = ap[0];
            a[1] = ap[8 * QPAD];
            a[2] = ap[4];
            a[3] = ap[8 * QPAD + 4];
#pragma unroll
            for (int nf = 0; nf < 8; nf++) {
                uint32_t bf[2];
                const uint32_t* bp = Ku + (nf * 8 + quad) * KPAD + kd * 8 + qt;
                bf[0] = bp[0];
                bf[1] = bp[4];
                mma_tf32(sacc[nf], a, bf);
            }
        }

        // ---- mask + online softmax (rows r0, r0+8) ----
#pragma unroll
        for (int r = 0; r < 2; r++) {
            const int qr = q0 + r0 + r * 8;
            const int* mrow = Mb + (size_t)qr * SEQ + kt;
            float p[16];
            float mx = -INFINITY;
#pragma unroll
            for (int nf = 0; nf < 8; nf++) {
                int2 mv = *(const int2*)(mrow + nf * 8 + qt * 2);
                float s0 = mv.x ? sacc[nf][2 * r]     * 0.125f : -INFINITY;
                float s1 = mv.y ? sacc[nf][2 * r + 1] * 0.125f : -INFINITY;
                p[2 * nf]     = s0;
                p[2 * nf + 1] = s1;
                mx = fmaxf(mx, fmaxf(s0, s1));
            }
            mx = fmaxf(mx, __shfl_xor_sync(0xffffffffu, mx, 1));
            mx = fmaxf(mx, __shfl_xor_sync(0xffffffffu, mx, 2));
            const float mnew = fmaxf(mi[r], mx);
            const float al   = __expf(mi[r] - mnew);
            float rs = 0.f;
            float* prow = Ps + (size_t)(r0 + 8 * r) * PPAD;
#pragma unroll
            for (int nf = 0; nf < 8; nf++) {
                float e0 = __expf(p[2 * nf]     - mnew);
                float e1 = __expf(p[2 * nf + 1] - mnew);
                rs += e0 + e1;
                float2 st = make_float2(tf32r(e0), tf32r(e1));
                *(float2*)(prow + nf * 8 + qt * 2) = st;
            }
            rs += __shfl_xor_sync(0xffffffffu, rs, 1);
            rs += __shfl_xor_sync(0xffffffffu, rs, 2);
            li[r] = li[r] * al + rs;
            mi[r] = mnew;
#pragma unroll
            for (int nf = 0; nf < 8; nf++) {
                oacc[nf][2 * r]     *= al;
                oacc[nf][2 * r + 1] *= al;
            }
        }
        __syncwarp();   // P written/read by the same warp only

        // ---- PV: O[16q x 64d] += P[16x64] @ V[64x64] ----
        const uint32_t* Pu = (const uint32_t*)Ps;
        const uint32_t* Vu = (const uint32_t*)Vs;
#pragma unroll
        for (int kk = 0; kk < 8; kk++) {
            uint32_t a[4];
            const uint32_t* ap = Pu + r0 * PPAD + kk * 8 + qt;
            a[0] = ap[0];
            a[1] = ap[8 * PPAD];
            a[2] = ap[4];
            a[3] = ap[8 * PPAD + 4];
#pragma unroll
            for (int nf = 0; nf < 8; nf++) {
                uint32_t bf[2];
                const uint32_t* bp = Vu + (kk * 8 + qt) * VPAD + nf * 8 + quad;
                bf[0] = bp[0];
                bf[1] = bp[4 * VPAD];
                mma_tf32(oacc[nf], a, bf);
            }
        }
        __syncthreads();   // Ks/Vs consumed before next tile's load
    }

    // Epilogue: write this head's 64-col slice of AO
#pragma unroll
    for (int r = 0; r < 2; r++) {
        const int qr = q0 + r0 + 8 * r;
        const float inv = 1.f / li[r];
        float* dst = AO + ((size_t)b * SEQ + qr) * D_MODEL + h * DK;
#pragma unroll
        for (int nf = 0; nf < 8; nf++) {
            float2 o2 = make_float2(oacc[nf][2 * r] * inv, oacc[nf][2 * r + 1] * inv);
            *(float2*)(dst + nf * 8 + qt * 2) = o2;
        }
    }
}

// ---------------------------------------------------------------------------
extern "C" void kernel_launch(void* const* d_in, const int* in_sizes, int n_in,
                              void* d_out, int out_size)
{
    const float* q   = (const float*)d_in[0];
    const float* k   = (const float*)d_in[1];
    const float* v   = (const float*)d_in[2];
    const int*   msk = (const int*)  d_in[3];
    const float* w_q = (const float*)d_in[4];
    const float* b_q = (const float*)d_in[5];
    const float* w_k = (const float*)d_in[6];
    const float* b_k = (const float*)d_in[7];
    const float* w_v = (const float*)d_in[8];
    const float* b_v = (const float*)d_in[9];
    const float* w_o = (const float*)d_in[10];
    const float* b_o = (const float*)d_in[11];
    float* out = (float*)d_out;

    float *gQ, *gK, *gV, *gAO;
    cudaGetSymbolAddress((void**)&gQ,  g_Q);
    cudaGetSymbolAddress((void**)&gK,  g_K);
    cudaGetSymbolAddress((void**)&gV,  g_V);
    cudaGetSymbolAddress((void**)&gAO, g_AO);

    cudaFuncSetAttribute(attn_kernel, cudaFuncAttributeMaxDynamicSharedMemorySize, ATTN_SMEM);

    dim3 ggrid(D_MODEL / 128, M_TOT / 128);   // (8, 32)
    gemm_bias_kernel<1><<<ggrid, 256>>>(q, w_q, b_q, gQ);
    gemm_bias_kernel<1><<<ggrid, 256>>>(k, w_k, b_k, gK);
    gemm_bias_kernel<1><<<ggrid, 256>>>(v, w_v, b_v, gV);

    dim3 agrid(SEQ / 128, BATCH * NHEAD);     // (16, 32)
    attn_kernel<<<agrid, 256, ATTN_SMEM>>>(msk, gAO);

    gemm_bias_kernel<0><<<ggrid, 256>>>(gAO, w_o, b_o, out);
}

// round 9
// speedup vs baseline: 4.9588x; 1.7009x over previous
#include <cuda_runtime.h>
#include <math.h>
#include <stdint.h>

#define D_MODEL 1024
#define NHEAD   16
#define DK      64
#define BATCH   2
#define SEQ     2048
#define M_TOT   (BATCH*SEQ)   // 4096

// Scratch (allocation-free rule: __device__ globals)
__device__ float g_Q [BATCH*NHEAD*SEQ*DK];   // [B,H,S,DK]
__device__ float g_K [BATCH*NHEAD*SEQ*DK];
__device__ float g_V [BATCH*NHEAD*SEQ*DK];
__device__ float g_AO[BATCH*SEQ*D_MODEL];    // merged attention output [B,S,D]

// ---------------------------------------------------------------------------
// Helpers
// ---------------------------------------------------------------------------
__device__ __forceinline__ float tf32r(float x) {
    uint32_t r;
    asm("cvt.rna.tf32.f32 %0, %1;" : "=r"(r) : "f"(x));
    return __uint_as_float(r);
}

// mma.sync m16n8k8 tf32 (sm_80+ baseline PTX -> HMMA on sm_103)
__device__ __forceinline__ void mma_tf32(float* d, const uint32_t* a, const uint32_t* b) {
    asm volatile(
        "mma.sync.aligned.m16n8k8.row.col.f32.tf32.tf32.f32 "
        "{%0,%1,%2,%3}, {%4,%5,%6,%7}, {%8,%9}, {%0,%1,%2,%3};"
        : "+f"(d[0]), "+f"(d[1]), "+f"(d[2]), "+f"(d[3])
        : "r"(a[0]), "r"(a[1]), "r"(a[2]), "r"(a[3]), "r"(b[0]), "r"(b[1]));
}

// ---------------------------------------------------------------------------
// Tensor-core GEMM (mma.sync tf32): C = A[M,1024] @ W[1024,1024]^T + bias
// CTA 128x128, 8 warps (2m x 4n), warp tile 64x32, K-stage 32, double buffer.
// MODE 0: C row-major [M,1024]
// MODE 1: head-split write into [B,H,S,64]
// ---------------------------------------------------------------------------
#define GPAD 36
#define GEMM_SMEM (4 * 128 * GPAD * 4)   // 2 bufs x (A+B) x 128 rows x GPAD

template<int MODE>
__global__ void __launch_bounds__(256) gemm_mma(
    const float* __restrict__ A, const float* __restrict__ W,
    const float* __restrict__ bias, float* __restrict__ C)
{
    constexpr int K = 1024;
    extern __shared__ float smg[];
    float* Ab[2] = { smg,                smg + 2 * 128 * GPAD };
    float* Bb[2] = { smg + 128 * GPAD,   smg + 3 * 128 * GPAD };

    const int tid  = threadIdx.x;
    const int wid  = tid >> 5;
    const int lane = tid & 31;
    const int quad = lane >> 2;
    const int qt   = lane & 3;
    const int wm   = wid >> 2;      // 0..1
    const int wn   = wid & 3;       // 0..3
    const int m0   = blockIdx.y * 128;
    const int n0   = blockIdx.x * 128;

    float acc[4][4][4];
#pragma unroll
    for (int mf = 0; mf < 4; mf++)
#pragma unroll
        for (int nf = 0; nf < 4; nf++)
#pragma unroll
            for (int j = 0; j < 4; j++) acc[mf][nf][j] = 0.f;

    // Per-thread staging coords: 4 float4 per matrix per stage.
    // f = tid + t*256 ; row = f>>3 ; c4 = (f&7)*4
    float4 ra[4], rb[4];

    // Prologue: load stage 0
#pragma unroll
    for (int t = 0; t < 4; t++) {
        int f = tid + t * 256, row = f >> 3, c4 = (f & 7) * 4;
        ra[t] = *(const float4*)(A + (size_t)(m0 + row) * K + c4);
        rb[t] = *(const float4*)(W + (size_t)(n0 + row) * K + c4);
    }
#pragma unroll
    for (int t = 0; t < 4; t++) {
        int f = tid + t * 256, row = f >> 3, c4 = (f & 7) * 4;
        float4 va = ra[t], vb = rb[t];
        va.x = tf32r(va.x); va.y = tf32r(va.y); va.z = tf32r(va.z); va.w = tf32r(va.w);
        vb.x = tf32r(vb.x); vb.y = tf32r(vb.y); vb.z = tf32r(vb.z); vb.w = tf32r(vb.w);
        *(float4*)(Ab[0] + row * GPAD + c4) = va;
        *(float4*)(Bb[0] + row * GPAD + c4) = vb;
    }
    __syncthreads();

    for (int s = 0; s < K / 32; s++) {
        const int cur = s & 1;
        // Prefetch next stage from gmem
        if (s + 1 < K / 32) {
            const int k0 = (s + 1) * 32;
#pragma unroll
            for (int t = 0; t < 4; t++) {
                int f = tid + t * 256, row = f >> 3, c4 = (f & 7) * 4;
                ra[t] = *(const float4*)(A + (size_t)(m0 + row) * K + k0 + c4);
                rb[t] = *(const float4*)(W + (size_t)(n0 + row) * K + k0 + c4);
            }
        }

        // Compute on current buffers
        const uint32_t* Au = (const uint32_t*)Ab[cur];
        const uint32_t* Bu = (const uint32_t*)Bb[cur];
#pragma unroll
        for (int kd = 0; kd < 4; kd++) {
            uint32_t af[4][4];
#pragma unroll
            for (int mf = 0; mf < 4; mf++) {
                const uint32_t* ap = Au + (wm * 64 + mf * 16 + quad) * GPAD + kd * 8 + qt;
                af[mf][0] = ap[0];
                af[mf][1] = ap[8 * GPAD];
                af[mf][2] = ap[4];
                af[mf][3] = ap[8 * GPAD + 4];
            }
            uint32_t bf[4][2];
#pragma unroll
            for (int nf = 0; nf < 4; nf++) {
                const uint32_t* bp = Bu + (wn * 32 + nf * 8 + quad) * GPAD + kd * 8 + qt;
                bf[nf][0] = bp[0];
                bf[nf][1] = bp[4];
            }
#pragma unroll
            for (int mf = 0; mf < 4; mf++)
#pragma unroll
                for (int nf = 0; nf < 4; nf++)
                    mma_tf32(acc[mf][nf], af[mf], bf[nf]);
        }

        // Stage next into the other buffer
        if (s + 1 < K / 32) {
            float* An = Ab[cur ^ 1];
            float* Bn = Bb[cur ^ 1];
#pragma unroll
            for (int t = 0; t < 4; t++) {
                int f = tid + t * 256, row = f >> 3, c4 = (f & 7) * 4;
                float4 va = ra[t], vb = rb[t];
                va.x = tf32r(va.x); va.y = tf32r(va.y); va.z = tf32r(va.z); va.w = tf32r(va.w);
                vb.x = tf32r(vb.x); vb.y = tf32r(vb.y); vb.z = tf32r(vb.z); vb.w = tf32r(vb.w);
                *(float4*)(An + row * GPAD + c4) = va;
                *(float4*)(Bn + row * GPAD + c4) = vb;
            }
        }
        __syncthreads();
    }

    // Epilogue
#pragma unroll
    for (int mf = 0; mf < 4; mf++) {
#pragma unroll
        for (int nf = 0; nf < 4; nf++) {
            const int col = n0 + wn * 32 + nf * 8 + qt * 2;
            const float b0 = bias[col], b1 = bias[col + 1];
#pragma unroll
            for (int jr = 0; jr < 2; jr++) {
                const int m = m0 + wm * 64 + mf * 16 + quad + 8 * jr;
                float2 v = make_float2(acc[mf][nf][2 * jr] + b0,
                                       acc[mf][nf][2 * jr + 1] + b1);
                if (MODE == 0) {
                    *(float2*)(C + (size_t)m * D_MODEL + col) = v;
                } else {
                    const int b  = m >> 11;
                    const int sq = m & (SEQ - 1);
                    const int h  = col >> 6;
                    const int dk = col & (DK - 1);
                    *(float2*)(C + (((size_t)(b * NHEAD + h) * SEQ + sq) * DK + dk)) = v;
                }
            }
        }
    }
}

// ---------------------------------------------------------------------------
// Flash attention with mma.sync tf32 (m16n8k8). (unchanged from R7, proven)
// ---------------------------------------------------------------------------
#define QPAD 68
#define KPAD 68
#define VPAD 72
#define PPAD 68
#define ATTN_SMEM ((128*QPAD + 64*KPAD + 64*VPAD + 128*PPAD) * 4)

__global__ void __launch_bounds__(256) attn_kernel(
    const int* __restrict__ mask, float* __restrict__ AO)
{
    extern __shared__ float sf[];
    float* Qs = sf;                       // [128][QPAD] row-major [q][d]
    float* Ks = Qs + 128 * QPAD;          // [64][KPAD]  [key][d]
    float* Vs = Ks + 64 * KPAD;           // [64][VPAD]  [key][d]
    float* Ps = Vs + 64 * VPAD;           // [128][PPAD] [q][key]

    const int tid  = threadIdx.x;
    const int w    = tid >> 5;
    const int lane = tid & 31;
    const int quad = lane >> 2;
    const int qt   = lane & 3;
    const int bh   = blockIdx.y;
    const int b    = bh >> 4;
    const int h    = bh & 15;
    const int q0   = blockIdx.x * 128;
    const int r0   = w * 16 + quad;

    const float* Qg = g_Q + ((size_t)bh * SEQ + q0) * DK;
    const float* Kg = g_K + (size_t)bh * SEQ * DK;
    const float* Vg = g_V + (size_t)bh * SEQ * DK;
    const int*   Mb = mask + (size_t)b * SEQ * SEQ;

#pragma unroll
    for (int t = 0; t < 8; t++) {
        int f  = tid + t * 256;
        int m  = f >> 4;
        int c4 = (f & 15) * 4;
        float4 v = *(const float4*)(Qg + (size_t)m * DK + c4);
        v.x = tf32r(v.x); v.y = tf32r(v.y); v.z = tf32r(v.z); v.w = tf32r(v.w);
        *(float4*)(Qs + m * QPAD + c4) = v;
    }

    float oacc[8][4];
#pragma unroll
    for (int nf = 0; nf < 8; nf++)
#pragma unroll
        for (int j = 0; j < 4; j++) oacc[nf][j] = 0.f;
    float mi[2] = {-INFINITY, -INFINITY};
    float li[2] = {0.f, 0.f};

    for (int kt = 0; kt < SEQ; kt += 64) {
#pragma unroll
        for (int t = 0; t < 4; t++) {
            int f   = tid + t * 256;
            int key = f >> 4;
            int c4  = (f & 15) * 4;
            float4 kv = *(const float4*)(Kg + (size_t)(kt + key) * DK + c4);
            kv.x = tf32r(kv.x); kv.y = tf32r(kv.y); kv.z = tf32r(kv.z); kv.w = tf32r(kv.w);
            *(float4*)(Ks + key * KPAD + c4) = kv;
            float4 vv = *(const float4*)(Vg + (size_t)(kt + key) * DK + c4);
            vv.x = tf32r(vv.x); vv.y = tf32r(vv.y); vv.z = tf32r(vv.z); vv.w = tf32r(vv.w);
            *(float4*)(Vs + key * VPAD + c4) = vv;
        }
        __syncthreads();

        float sacc[8][4];
#pragma unroll
        for (int nf = 0; nf < 8; nf++)
#pragma unroll
            for (int j = 0; j < 4; j++) sacc[nf][j] = 0.f;

        const uint32_t* Qu = (const uint32_t*)Qs;
        const uint32_t* Ku = (const uint32_t*)Ks;
#pragma unroll
        for (int kd = 0; kd < 8; kd++) {
            uint32_t a[4];
            const uint32_t* ap = Qu + r0 * QPAD + kd * 8 + qt;
            a[0] = ap[0];
            a[1] = ap[8 * QPAD];
            a[2] = ap[4];
            a[3] = ap[8 * QPAD + 4];
#pragma unroll
            for (int nf = 0; nf < 8; nf++) {
                uint32_t bfr[2];
                const uint32_t* bp = Ku + (nf * 8 + quad) * KPAD + kd * 8 + qt;
                bfr[0] = bp[0];
                bfr[1] = bp[4];
                mma_tf32(sacc[nf], a, bfr);
            }
        }

#pragma unroll
        for (int r = 0; r < 2; r++) {
            const int qr = q0 + r0 + r * 8;
            const int* mrow = Mb + (size_t)qr * SEQ + kt;
            float p[16];
            float mx = -INFINITY;
#pragma unroll
            for (int nf = 0; nf < 8; nf++) {
                int2 mv = *(const int2*)(mrow + nf * 8 + qt * 2);
                float s0 = mv.x ? sacc[nf][2 * r]     * 0.125f : -INFINITY;
                float s1 = mv.y ? sacc[nf][2 * r + 1] * 0.125f : -INFINITY;
                p[2 * nf]     = s0;
                p[2 * nf + 1] = s1;
                mx = fmaxf(mx, fmaxf(s0, s1));
            }
            mx = fmaxf(mx, __shfl_xor_sync(0xffffffffu, mx, 1));
            mx = fmaxf(mx, __shfl_xor_sync(0xffffffffu, mx, 2));
            const float mnew = fmaxf(mi[r], mx);
            const float al   = __expf(mi[r] - mnew);
            float rs = 0.f;
            float* prow = Ps + (size_t)(r0 + 8 * r) * PPAD;
#pragma unroll
            for (int nf = 0; nf < 8; nf++) {
                float e0 = __expf(p[2 * nf]     - mnew);
                float e1 = __expf(p[2 * nf + 1] - mnew);
                rs += e0 + e1;
                float2 st = make_float2(tf32r(e0), tf32r(e1));
                *(float2*)(prow + nf * 8 + qt * 2) = st;
            }
            rs += __shfl_xor_sync(0xffffffffu, rs, 1);
            rs += __shfl_xor_sync(0xffffffffu, rs, 2);
            li[r] = li[r] * al + rs;
            mi[r] = mnew;
#pragma unroll
            for (int nf = 0; nf < 8; nf++) {
                oacc[nf][2 * r]     *= al;
                oacc[nf][2 * r + 1] *= al;
            }
        }
        __syncwarp();

        const uint32_t* Pu = (const uint32_t*)Ps;
        const uint32_t* Vu = (const uint32_t*)Vs;
#pragma unroll
        for (int kk = 0; kk < 8; kk++) {
            uint32_t a[4];
            const uint32_t* ap = Pu + r0 * PPAD + kk * 8 + qt;
            a[0] = ap[0];
            a[1] = ap[8 * PPAD];
            a[2] = ap[4];
            a[3] = ap[8 * PPAD + 4];
#pragma unroll
            for (int nf = 0; nf < 8; nf++) {
                uint32_t bfr[2];
                const uint32_t* bp = Vu + (kk * 8 + qt) * VPAD + nf * 8 + quad;
                bfr[0] = bp[0];
                bfr[1] = bp[4 * VPAD];
                mma_tf32(oacc[nf], a, bfr);
            }
        }
        __syncthreads();
    }

#pragma unroll
    for (int r = 0; r < 2; r++) {
        const int qr = q0 + r0 + 8 * r;
        const float inv = 1.f / li[r];
        float* dst = AO + ((size_t)b * SEQ + qr) * D_MODEL + h * DK;
#pragma unroll
        for (int nf = 0; nf < 8; nf++) {
            float2 o2 = make_float2(oacc[nf][2 * r] * inv, oacc[nf][2 * r + 1] * inv);
            *(float2*)(dst + nf * 8 + qt * 2) = o2;
        }
    }
}

// ---------------------------------------------------------------------------
extern "C" void kernel_launch(void* const* d_in, const int* in_sizes, int n_in,
                              void* d_out, int out_size)
{
    const float* q   = (const float*)d_in[0];
    const float* k   = (const float*)d_in[1];
    const float* v   = (const float*)d_in[2];
    const int*   msk = (const int*)  d_in[3];
    const float* w_q = (const float*)d_in[4];
    const float* b_q = (const float*)d_in[5];
    const float* w_k = (const float*)d_in[6];
    const float* b_k = (const float*)d_in[7];
    const float* w_v = (const float*)d_in[8];
    const float* b_v = (const float*)d_in[9];
    const float* w_o = (const float*)d_in[10];
    const float* b_o = (const float*)d_in[11];
    float* out = (float*)d_out;

    float *gQ, *gK, *gV, *gAO;
    cudaGetSymbolAddress((void**)&gQ,  g_Q);
    cudaGetSymbolAddress((void**)&gK,  g_K);
    cudaGetSymbolAddress((void**)&gV,  g_V);
    cudaGetSymbolAddress((void**)&gAO, g_AO);

    cudaFuncSetAttribute(gemm_mma<0>, cudaFuncAttributeMaxDynamicSharedMemorySize, GEMM_SMEM);
    cudaFuncSetAttribute(gemm_mma<1>, cudaFuncAttributeMaxDynamicSharedMemorySize, GEMM_SMEM);
    cudaFuncSetAttribute(attn_kernel, cudaFuncAttributeMaxDynamicSharedMemorySize, ATTN_SMEM);

    dim3 ggrid(D_MODEL / 128, M_TOT / 128);   // (8, 32)
    gemm_mma<1><<<ggrid, 256, GEMM_SMEM>>>(q, w_q, b_q, gQ);
    gemm_mma<1><<<ggrid, 256, GEMM_SMEM>>>(k, w_k, b_k, gK);
    gemm_mma<1><<<ggrid, 256, GEMM_SMEM>>>(v, w_v, b_v, gV);

    dim3 agrid(SEQ / 128, BATCH * NHEAD);     // (16, 32)
    attn_kernel<<<agrid, 256, ATTN_SMEM>>>(msk, gAO);

    gemm_mma<0><<<ggrid, 256, GEMM_SMEM>>>(gAO, w_o, b_o, out);
}

// round 10
// speedup vs baseline: 6.5263x; 1.3161x over previous
#include <cuda_runtime.h>
#include <cuda_fp16.h>
#include <math.h>
#include <stdint.h>

#define D_MODEL 1024
#define NHEAD   16
#define DK      64
#define BATCH   2
#define SEQ     2048
#define M_TOT   (BATCH*SEQ)   // 4096

// Scratch (allocation-free rule: __device__ globals). fp16 pairs as uint32.
__device__ uint32_t g_Qh [BATCH*NHEAD*SEQ*(DK/2)];       // [bh][s][32 pairs(d)]
__device__ uint32_t g_Kh [BATCH*NHEAD*SEQ*(DK/2)];       // [bh][s][32 pairs(d)]
__device__ uint32_t g_Vth[BATCH*NHEAD*DK*(SEQ/2)];       // [bh][d][1024 pairs(s)]
__device__ float    g_AO [BATCH*SEQ*D_MODEL];            // attention out fp32

// ---------------------------------------------------------------------------
// Helpers
// ---------------------------------------------------------------------------
__device__ __forceinline__ uint32_t pk2(float a, float b) {
    __half2 h = __floats2half2_rn(a, b);   // .x = a (low half)
    return *(uint32_t*)&h;
}

// mma.sync m16n8k16 fp16 in, fp32 acc (sm_80+ baseline PTX)
__device__ __forceinline__ void mma_f16(float* d, const uint32_t* a, const uint32_t* b) {
    asm volatile(
        "mma.sync.aligned.m16n8k16.row.col.f32.f16.f16.f32 "
        "{%0,%1,%2,%3}, {%4,%5,%6,%7}, {%8,%9}, {%0,%1,%2,%3};"
        : "+f"(d[0]), "+f"(d[1]), "+f"(d[2]), "+f"(d[3])
        : "r"(a[0]), "r"(a[1]), "r"(a[2]), "r"(a[3]), "r"(b[0]), "r"(b[1]));
}

// ---------------------------------------------------------------------------
// fp16 tensor-core GEMM body: C = A[M,1024] @ W[1024,1024]^T + bias
// CTA 128x128, 8 warps (2m x 4n), warp tile 64x32, K-stage 32 fp32 elems
// (= 16 pairs), double-buffered smem of fp16 pairs.
// mode 0: C fp32 row-major [M,1024]
// mode 1: C fp16 pairs, head-split [bh][s][32 pairs]   (bias by col)
// mode 2: C fp16 pairs, Vt layout  [bh][d][s/2 pairs]  (bias by ROW m)
// ---------------------------------------------------------------------------
#define GP 20                               // pairs per row + pad (uint32)
#define GEMM_SMEM (4 * 128 * GP * 4)        // 2 bufs x (A+B) x 128 x GP x 4B

__device__ __forceinline__ void gemm_body(
    const float* __restrict__ A, const float* __restrict__ W,
    const float* __restrict__ bias, void* __restrict__ C,
    int mode, int m0, int n0, uint32_t* su)
{
    constexpr int K = 1024;
    uint32_t* Ab[2] = { su,                su + 2 * 128 * GP };
    uint32_t* Bb[2] = { su + 128 * GP,     su + 3 * 128 * GP };

    const int tid  = threadIdx.x;
    const int wid  = tid >> 5;
    const int lane = tid & 31;
    const int quad = lane >> 2;
    const int qt   = lane & 3;
    const int wm   = wid >> 2;
    const int wn   = wid & 3;

    float acc[4][4][4];
#pragma unroll
    for (int mf = 0; mf < 4; mf++)
#pragma unroll
        for (int nf = 0; nf < 4; nf++)
#pragma unroll
            for (int j = 0; j < 4; j++) acc[mf][nf][j] = 0.f;

    float4 ra[4], rb[4];
    // Prologue: stage 0 (k 0..31). 1024 float4 slots per matrix; 4/thread.
#pragma unroll
    for (int t = 0; t < 4; t++) {
        int f = tid + t * 256, row = f >> 3, c4 = (f & 7) * 4;
        ra[t] = *(const float4*)(A + (size_t)(m0 + row) * K + c4);
        rb[t] = *(const float4*)(W + (size_t)(n0 + row) * K + c4);
    }
#pragma unroll
    for (int t = 0; t < 4; t++) {
        int f = tid + t * 256, row = f >> 3, p2 = (f & 7) * 2;
        *(uint2*)(Ab[0] + row * GP + p2) = make_uint2(pk2(ra[t].x, ra[t].y), pk2(ra[t].z, ra[t].w));
        *(uint2*)(Bb[0] + row * GP + p2) = make_uint2(pk2(rb[t].x, rb[t].y), pk2(rb[t].z, rb[t].w));
    }
    __syncthreads();

    for (int s = 0; s < K / 32; s++) {
        const int cur = s & 1;
        if (s + 1 < K / 32) {
            const int k0 = (s + 1) * 32;
#pragma unroll
            for (int t = 0; t < 4; t++) {
                int f = tid + t * 256, row = f >> 3, c4 = (f & 7) * 4;
                ra[t] = *(const float4*)(A + (size_t)(m0 + row) * K + k0 + c4);
                rb[t] = *(const float4*)(W + (size_t)(n0 + row) * K + k0 + c4);
            }
        }

        const uint32_t* Au = Ab[cur];
        const uint32_t* Bu = Bb[cur];
#pragma unroll
        for (int kd = 0; kd < 2; kd++) {        // two k16 chunks per stage
            uint32_t af[4][4];
#pragma unroll
            for (int mf = 0; mf < 4; mf++) {
                const uint32_t* ap = Au + (wm * 64 + mf * 16 + quad) * GP + kd * 8 + qt;
                af[mf][0] = ap[0];
                af[mf][1] = ap[8 * GP];
                af[mf][2] = ap[4];
                af[mf][3] = ap[8 * GP + 4];
            }
            uint32_t bf[4][2];
#pragma unroll
            for (int nf = 0; nf < 4; nf++) {
                const uint32_t* bp = Bu + (wn * 32 + nf * 8 + quad) * GP + kd * 8 + qt;
                bf[nf][0] = bp[0];
                bf[nf][1] = bp[4];
            }
#pragma unroll
            for (int mf = 0; mf < 4; mf++)
#pragma unroll
                for (int nf = 0; nf < 4; nf++)
                    mma_f16(acc[mf][nf], af[mf], bf[nf]);
        }

        if (s + 1 < K / 32) {
            uint32_t* An = Ab[cur ^ 1];
            uint32_t* Bn = Bb[cur ^ 1];
#pragma unroll
            for (int t = 0; t < 4; t++) {
                int f = tid + t * 256, row = f >> 3, p2 = (f & 7) * 2;
                *(uint2*)(An + row * GP + p2) = make_uint2(pk2(ra[t].x, ra[t].y), pk2(ra[t].z, ra[t].w));
                *(uint2*)(Bn + row * GP + p2) = make_uint2(pk2(rb[t].x, rb[t].y), pk2(rb[t].z, rb[t].w));
            }
        }
        __syncthreads();
    }

    // Epilogue
#pragma unroll
    for (int mf = 0; mf < 4; mf++) {
#pragma unroll
        for (int nf = 0; nf < 4; nf++) {
            const int col = n0 + wn * 32 + nf * 8 + qt * 2;
#pragma unroll
            for (int jr = 0; jr < 2; jr++) {
                const int m = m0 + wm * 64 + mf * 16 + quad + 8 * jr;
                float v0 = acc[mf][nf][2 * jr];
                float v1 = acc[mf][nf][2 * jr + 1];
                if (mode == 0) {
                    v0 += bias[col]; v1 += bias[col + 1];
                    *(float2*)((float*)C + (size_t)m * D_MODEL + col) = make_float2(v0, v1);
                } else if (mode == 1) {
                    v0 += bias[col]; v1 += bias[col + 1];
                    const int bb = m >> 11, sq = m & (SEQ - 1);
                    const int h = col >> 6, pairp = (col & 63) >> 1;
                    ((uint32_t*)C)[((size_t)(bb * NHEAD + h) * SEQ + sq) * (DK/2) + pairp] = pk2(v0, v1);
                } else {   // mode 2: m = d-row, col = s
                    const float bv = bias[m];
                    v0 += bv; v1 += bv;
                    const int bb = col >> 11, sq = col & (SEQ - 1);
                    const int h = m >> 6, dk = m & (DK - 1);
                    ((uint32_t*)C)[((size_t)(bb * NHEAD + h) * DK + dk) * (SEQ/2) + (sq >> 1)] = pk2(v0, v1);
                }
            }
        }
    }
}

// Fused Q/K/V projections: z=0 Q, z=1 K, z=2 V(transposed output).
__global__ void __launch_bounds__(256) gemm_qkv(
    const float* __restrict__ q,  const float* __restrict__ k,  const float* __restrict__ v,
    const float* __restrict__ wq, const float* __restrict__ wk, const float* __restrict__ wv,
    const float* __restrict__ bq, const float* __restrict__ bk, const float* __restrict__ bv,
    uint32_t* outQ, uint32_t* outK, uint32_t* outVt)
{
    extern __shared__ uint32_t su[];
    const int z = blockIdx.z;
    if (z == 0) {
        gemm_body(q, wq, bq, outQ, 1, blockIdx.y * 128, blockIdx.x * 128, su);
    } else if (z == 1) {
        gemm_body(k, wk, bk, outK, 1, blockIdx.y * 128, blockIdx.x * 128, su);
    } else {
        // Vt = Wv @ v^T : A = wv (M=1024 rows of d), W-operand = v (N=4096 rows of s)
        gemm_body(wv, v, bv, outVt, 2, blockIdx.x * 128, blockIdx.y * 128, su);
    }
}

// Output projection: fp32 in (AO), fp32 out.
__global__ void __launch_bounds__(256) gemm_out(
    const float* __restrict__ A, const float* __restrict__ W,
    const float* __restrict__ bias, float* __restrict__ C)
{
    extern __shared__ uint32_t su[];
    gemm_body(A, W, bias, C, 0, blockIdx.y * 128, blockIdx.x * 128, su);
}

// ---------------------------------------------------------------------------
// Flash attention, fp16 mma.m16n8k16.
// CTA: 128 q-rows x one (b,h), 8 warps, warp = 16 q-rows x 64 keys.
// All tiles stored as fp16 pairs (uint32). V is pre-transposed in gmem.
// ---------------------------------------------------------------------------
#define QP 36
#define KP 36
#define VP 36
#define PP 36
#define ATTN_SMEM ((128*QP + 64*KP + 64*VP + 128*PP) * 4)

__global__ void __launch_bounds__(256) attn_kernel(
    const int* __restrict__ mask, float* __restrict__ AO)
{
    extern __shared__ uint32_t su[];
    uint32_t* Qp = su;                 // [128][QP]  pairs along d
    uint32_t* Kp = Qp + 128 * QP;      // [64][KP]   pairs along d
    uint32_t* Vp = Kp + 64 * KP;       // [64][VP]   Vt: [d][pairs along key]
    uint32_t* Pp = Vp + 64 * VP;       // [128][PP]  pairs along key

    const int tid  = threadIdx.x;
    const int w    = tid >> 5;
    const int lane = tid & 31;
    const int quad = lane >> 2;
    const int qt   = lane & 3;
    const int bh   = blockIdx.y;
    const int b    = bh >> 4;
    const int h    = bh & 15;
    const int q0   = blockIdx.x * 128;
    const int r0   = w * 16 + quad;

    const uint32_t* Qg = g_Qh  + ((size_t)bh * SEQ + q0) * (DK/2);
    const uint32_t* Kg = g_Kh  + (size_t)bh * SEQ * (DK/2);
    const uint32_t* Vg = g_Vth + (size_t)bh * DK * (SEQ/2);
    const int*      Mb = mask + (size_t)b * SEQ * SEQ;

    // Stage Q once: 128 rows x 32 pairs = 4096 u32 -> 8 uint2/thread
#pragma unroll
    for (int t = 0; t < 8; t++) {
        int f = tid + t * 256, row = f >> 4, c2 = (f & 15) * 2;
        *(uint2*)(Qp + row * QP + c2) = *(const uint2*)(Qg + (size_t)row * (DK/2) + c2);
    }

    float oacc[8][4];
#pragma unroll
    for (int nf = 0; nf < 8; nf++)
#pragma unroll
        for (int j = 0; j < 4; j++) oacc[nf][j] = 0.f;
    float mi[2] = {-INFINITY, -INFINITY};
    float li[2] = {0.f, 0.f};

    for (int kt = 0; kt < SEQ; kt += 64) {
        // Stage K tile [64 keys][32 pairs] and Vt tile [64 d][32 keypairs]
#pragma unroll
        for (int t = 0; t < 4; t++) {
            int f = tid + t * 256, row = f >> 4, c2 = (f & 15) * 2;
            *(uint2*)(Kp + row * KP + c2) =
                *(const uint2*)(Kg + (size_t)(kt + row) * (DK/2) + c2);
            *(uint2*)(Vp + row * VP + c2) =
                *(const uint2*)(Vg + (size_t)row * (SEQ/2) + (kt >> 1) + c2);
        }
        __syncthreads();

        // ---- QK^T: S[16q x 64k] per warp (4 k16 chunks) ----
        float sacc[8][4];
#pragma unroll
        for (int nf = 0; nf < 8; nf++)
#pragma unroll
            for (int j = 0; j < 4; j++) sacc[nf][j] = 0.f;

#pragma unroll
        for (int kd = 0; kd < 4; kd++) {
            uint32_t a[4];
            const uint32_t* ap = Qp + r0 * QP + kd * 8 + qt;
            a[0] = ap[0];
            a[1] = ap[8 * QP];
            a[2] = ap[4];
            a[3] = ap[8 * QP + 4];
#pragma unroll
            for (int nf = 0; nf < 8; nf++) {
                uint32_t bfr[2];
                const uint32_t* bp = Kp + (nf * 8 + quad) * KP + kd * 8 + qt;
                bfr[0] = bp[0];
                bfr[1] = bp[4];
                mma_f16(sacc[nf], a, bfr);
            }
        }

        // ---- mask + online softmax (rows r0, r0+8) ----
#pragma unroll
        for (int r = 0; r < 2; r++) {
            const int qr = q0 + r0 + r * 8;
            const int* mrow = Mb + (size_t)qr * SEQ + kt;
            float p[16];
            float mx = -INFINITY;
#pragma unroll
            for (int nf = 0; nf < 8; nf++) {
                int2 mv = *(const int2*)(mrow + nf * 8 + qt * 2);
                float s0 = mv.x ? sacc[nf][2 * r]     * 0.125f : -INFINITY;
                float s1 = mv.y ? sacc[nf][2 * r + 1] * 0.125f : -INFINITY;
                p[2 * nf]     = s0;
                p[2 * nf + 1] = s1;
                mx = fmaxf(mx, fmaxf(s0, s1));
            }
            mx = fmaxf(mx, __shfl_xor_sync(0xffffffffu, mx, 1));
            mx = fmaxf(mx, __shfl_xor_sync(0xffffffffu, mx, 2));
            const float mnew = fmaxf(mi[r], mx);
            const float al   = __expf(mi[r] - mnew);
            float rs = 0.f;
            uint32_t* prow = Pp + (size_t)(r0 + 8 * r) * PP;
#pragma unroll
            for (int nf = 0; nf < 8; nf++) {
                float e0 = __expf(p[2 * nf]     - mnew);
                float e1 = __expf(p[2 * nf + 1] - mnew);
                rs += e0 + e1;
                prow[nf * 4 + qt] = pk2(e0, e1);
            }
            rs += __shfl_xor_sync(0xffffffffu, rs, 1);
            rs += __shfl_xor_sync(0xffffffffu, rs, 2);
            li[r] = li[r] * al + rs;
            mi[r] = mnew;
#pragma unroll
            for (int nf = 0; nf < 8; nf++) {
                oacc[nf][2 * r]     *= al;
                oacc[nf][2 * r + 1] *= al;
            }
        }
        __syncwarp();   // P written/read by this warp only

        // ---- PV: O[16q x 64d] += P @ V (4 k16 chunks over keys) ----
#pragma unroll
        for (int kk = 0; kk < 4; kk++) {
            uint32_t a[4];
            const uint32_t* ap = Pp + r0 * PP + kk * 8 + qt;
            a[0] = ap[0];
            a[1] = ap[8 * PP];
            a[2] = ap[4];
            a[3] = ap[8 * PP + 4];
#pragma unroll
            for (int nf = 0; nf < 8; nf++) {
                uint32_t bfr[2];
                const uint32_t* bp = Vp + (nf * 8 + quad) * VP + kk * 8 + qt;
                bfr[0] = bp[0];
                bfr[1] = bp[4];
                mma_f16(oacc[nf], a, bfr);
            }
        }
        __syncthreads();
    }

    // Epilogue (fp32 AO)
#pragma unroll
    for (int r = 0; r < 2; r++) {
        const int qr = q0 + r0 + 8 * r;
        const float inv = 1.f / li[r];
        float* dst = AO + ((size_t)b * SEQ + qr) * D_MODEL + h * DK;
#pragma unroll
        for (int nf = 0; nf < 8; nf++) {
            float2 o2 = make_float2(oacc[nf][2 * r] * inv, oacc[nf][2 * r + 1] * inv);
            *(float2*)(dst + nf * 8 + qt * 2) = o2;
        }
    }
}

// ---------------------------------------------------------------------------
extern "C" void kernel_launch(void* const* d_in, const int* in_sizes, int n_in,
                              void* d_out, int out_size)
{
    const float* q   = (const float*)d_in[0];
    const float* k   = (const float*)d_in[1];
    const float* v   = (const float*)d_in[2];
    const int*   msk = (const int*)  d_in[3];
    const float* w_q = (const float*)d_in[4];
    const float* b_q = (const float*)d_in[5];
    const float* w_k = (const float*)d_in[6];
    const float* b_k = (const float*)d_in[7];
    const float* w_v = (const float*)d_in[8];
    const float* b_v = (const float*)d_in[9];
    const float* w_o = (const float*)d_in[10];
    const float* b_o = (const float*)d_in[11];
    float* out = (float*)d_out;

    uint32_t *gQ, *gK, *gVt;
    float *gAO;
    cudaGetSymbolAddress((void**)&gQ,  g_Qh);
    cudaGetSymbolAddress((void**)&gK,  g_Kh);
    cudaGetSymbolAddress((void**)&gVt, g_Vth);
    cudaGetSymbolAddress((void**)&gAO, g_AO);

    cudaFuncSetAttribute(gemm_qkv,   cudaFuncAttributeMaxDynamicSharedMemorySize, GEMM_SMEM);
    cudaFuncSetAttribute(gemm_out,   cudaFuncAttributeMaxDynamicSharedMemorySize, GEMM_SMEM);
    cudaFuncSetAttribute(attn_kernel, cudaFuncAttributeMaxDynamicSharedMemorySize, ATTN_SMEM);

    dim3 qkvgrid(8, 32, 3);
    gemm_qkv<<<qkvgrid, 256, GEMM_SMEM>>>(q, k, v, w_q, w_k, w_v, b_q, b_k, b_v,
                                          gQ, gK, gVt);

    dim3 agrid(SEQ / 128, BATCH * NHEAD);     // (16, 32)
    attn_kernel<<<agrid, 256, ATTN_SMEM>>>(msk, gAO);

    dim3 ogrid(8, 32);
    gemm_out<<<ogrid, 256, GEMM_SMEM>>>(gAO, w_o, b_o, out);
}

// round 11
// speedup vs baseline: 8.5203x; 1.3055x over previous
#include <cuda_runtime.h>
#include <cuda_fp16.h>
#include <math.h>
#include <stdint.h>

#define D_MODEL 1024
#define NHEAD   16
#define DK      64
#define BATCH   2
#define SEQ     2048
#define M_TOT   (BATCH*SEQ)   // 4096

// fp16 copies of inputs (pre-pass)
__device__ __half h_q [M_TOT*D_MODEL];
__device__ __half h_k [M_TOT*D_MODEL];
__device__ __half h_v [M_TOT*D_MODEL];
__device__ __half h_wq[D_MODEL*D_MODEL];
__device__ __half h_wk[D_MODEL*D_MODEL];
__device__ __half h_wv[D_MODEL*D_MODEL];
__device__ __half h_wo[D_MODEL*D_MODEL];
// intermediates (fp16 pairs as uint32)
__device__ uint32_t g_Qh [BATCH*NHEAD*SEQ*(DK/2)];   // [bh][s][32 pairs(d)]
__device__ uint32_t g_Kh [BATCH*NHEAD*SEQ*(DK/2)];   // [bh][s][32 pairs(d)]
__device__ uint32_t g_Vth[BATCH*NHEAD*DK*(SEQ/2)];   // [bh][d][1024 pairs(s)]
__device__ uint32_t g_AOh[M_TOT*(D_MODEL/2)];        // attention out, fp16 pairs

// ---------------------------------------------------------------------------
__device__ __forceinline__ uint32_t pk2(float a, float b) {
    __half2 h = __floats2half2_rn(a, b);
    return *(uint32_t*)&h;
}
__device__ __forceinline__ uint32_t smem_u32(const void* p) {
    uint32_t a;
    asm("{ .reg .u64 t; cvta.to.shared.u64 t, %1; cvt.u32.u64 %0, t; }" : "=r"(a) : "l"(p));
    return a;
}
__device__ __forceinline__ void mma_f16(float* d, const uint32_t* a, const uint32_t* b) {
    asm volatile(
        "mma.sync.aligned.m16n8k16.row.col.f32.f16.f16.f32 "
        "{%0,%1,%2,%3}, {%4,%5,%6,%7}, {%8,%9}, {%0,%1,%2,%3};"
        : "+f"(d[0]), "+f"(d[1]), "+f"(d[2]), "+f"(d[3])
        : "r"(a[0]), "r"(a[1]), "r"(a[2]), "r"(a[3]), "r"(b[0]), "r"(b[1]));
}
#define CP16(dst, src) \
    asm volatile("cp.async.cg.shared.global [%0], [%1], 16;" :: "r"(dst), "l"(src))
#define CP_COMMIT() asm volatile("cp.async.commit_group;" ::: "memory")
#define CP_WAIT(n)  asm volatile("cp.async.wait_group %0;" :: "n"(n) : "memory")

// ---------------------------------------------------------------------------
// fp32 -> fp16 conversion pre-pass
// ---------------------------------------------------------------------------
__global__ void to_half(const float4* __restrict__ src, uint2* __restrict__ dst, int n4) {
    int i = blockIdx.x * blockDim.x + threadIdx.x;
    if (i < n4) {
        float4 v = src[i];
        dst[i] = make_uint2(pk2(v.x, v.y), pk2(v.z, v.w));
    }
}

// ---------------------------------------------------------------------------
// fp16 cp.async GEMM body: C = A[M,1024] @ W[1024,1024]^T + bias
// CTA 128x128, 8 warps (2m x 4n), K-stage 32 halfs, 4-stage cp.async pipeline.
// mode 0: C fp32 row-major ; mode 1: fp16 pairs head-split [bh][s][d-pairs] ;
// mode 2: fp16 pairs Vt [bh][d][s-pairs] (bias by row m)
// ---------------------------------------------------------------------------
#define GP 20                     // u32 per smem row (16 pairs + pad)
#define NSTG 4
#define STG_U32 (2 * 128 * GP)    // A+B per stage
#define GEMM_SMEM (NSTG * STG_U32 * 4)   // 81920 B

__device__ __forceinline__ void gemm_issue(
    const __half* __restrict__ A, const __half* __restrict__ W,
    int m0, int n0, int k0, uint32_t sbase, int st)
{
    const int tid = threadIdx.x;
    const uint32_t abuf = sbase + (st * STG_U32) * 4;
    const uint32_t bbuf = abuf + 128 * GP * 4;
#pragma unroll
    for (int t = 0; t < 2; t++) {
        int c   = tid + t * 256;     // 0..511
        int row = c >> 2;
        int seg = c & 3;             // 16B segment
        CP16(abuf + (row * GP + seg * 4) * 4, A + (size_t)(m0 + row) * 1024 + k0 + seg * 8);
        CP16(bbuf + (row * GP + seg * 4) * 4, W + (size_t)(n0 + row) * 1024 + k0 + seg * 8);
    }
}

__device__ __forceinline__ void gemm_body(
    const __half* __restrict__ A, const __half* __restrict__ W,
    const float* __restrict__ bias, void* __restrict__ C,
    int mode, int m0, int n0, uint32_t* su)
{
    const uint32_t sbase = smem_u32(su);
    const int tid  = threadIdx.x;
    const int wid  = tid >> 5;
    const int lane = tid & 31;
    const int quad = lane >> 2;
    const int qt   = lane & 3;
    const int wm   = wid >> 2;
    const int wn   = wid & 3;

    float acc[4][4][4];
#pragma unroll
    for (int mf = 0; mf < 4; mf++)
#pragma unroll
        for (int nf = 0; nf < 4; nf++)
#pragma unroll
            for (int j = 0; j < 4; j++) acc[mf][nf][j] = 0.f;

    // Prologue: issue stages 0..NSTG-2
#pragma unroll
    for (int i = 0; i < NSTG - 1; i++) {
        gemm_issue(A, W, m0, n0, i * 32, sbase, i);
        CP_COMMIT();
    }

    for (int s = 0; s < 32; s++) {
        __syncthreads();   // everyone done computing stage s-1 (buffer reuse safety)
        if (s + NSTG - 1 < 32)
            gemm_issue(A, W, m0, n0, (s + NSTG - 1) * 32, sbase, (s + NSTG - 1) % NSTG);
        CP_COMMIT();       // unconditional: keeps group count exact at tail
        CP_WAIT(NSTG - 1); // stage s arrived
        __syncthreads();   // visibility across threads

        const uint32_t* Au = su + (s % NSTG) * STG_U32;
        const uint32_t* Bu = Au + 128 * GP;
#pragma unroll
        for (int kd = 0; kd < 2; kd++) {
            uint32_t af[4][4];
#pragma unroll
            for (int mf = 0; mf < 4; mf++) {
                const uint32_t* ap = Au + (wm * 64 + mf * 16 + quad) * GP + kd * 8 + qt;
                af[mf][0] = ap[0];
                af[mf][1] = ap[8 * GP];
                af[mf][2] = ap[4];
                af[mf][3] = ap[8 * GP + 4];
            }
            uint32_t bf[4][2];
#pragma unroll
            for (int nf = 0; nf < 4; nf++) {
                const uint32_t* bp = Bu + (wn * 32 + nf * 8 + quad) * GP + kd * 8 + qt;
                bf[nf][0] = bp[0];
                bf[nf][1] = bp[4];
            }
#pragma unroll
            for (int mf = 0; mf < 4; mf++)
#pragma unroll
                for (int nf = 0; nf < 4; nf++)
                    mma_f16(acc[mf][nf], af[mf], bf[nf]);
        }
    }

    // Epilogue
#pragma unroll
    for (int mf = 0; mf < 4; mf++) {
#pragma unroll
        for (int nf = 0; nf < 4; nf++) {
            const int col = n0 + wn * 32 + nf * 8 + qt * 2;
#pragma unroll
            for (int jr = 0; jr < 2; jr++) {
                const int m = m0 + wm * 64 + mf * 16 + quad + 8 * jr;
                float v0 = acc[mf][nf][2 * jr];
                float v1 = acc[mf][nf][2 * jr + 1];
                if (mode == 0) {
                    v0 += bias[col]; v1 += bias[col + 1];
                    *(float2*)((float*)C + (size_t)m * D_MODEL + col) = make_float2(v0, v1);
                } else if (mode == 1) {
                    v0 += bias[col]; v1 += bias[col + 1];
                    const int bb = m >> 11, sq = m & (SEQ - 1);
                    const int h = col >> 6, pairp = (col & 63) >> 1;
                    ((uint32_t*)C)[((size_t)(bb * NHEAD + h) * SEQ + sq) * (DK/2) + pairp] = pk2(v0, v1);
                } else {   // mode 2: m = d-row, col = s
                    const float bv = bias[m];
                    v0 += bv; v1 += bv;
                    const int bb = col >> 11, sq = col & (SEQ - 1);
                    const int h = m >> 6, dk = m & (DK - 1);
                    ((uint32_t*)C)[((size_t)(bb * NHEAD + h) * DK + dk) * (SEQ/2) + (sq >> 1)] = pk2(v0, v1);
                }
            }
        }
    }
}

// Fused Q/K/V projections: z=0 Q, z=1 K, z=2 V(transposed output).
__global__ void __launch_bounds__(256, 2) gemm_qkv(
    uint32_t* outQ, uint32_t* outK, uint32_t* outVt,
    const float* __restrict__ bq, const float* __restrict__ bk, const float* __restrict__ bv)
{
    extern __shared__ uint32_t su[];
    const int z = blockIdx.z;
    if (z == 0)      gemm_body(h_q,  h_wq, bq, outQ,  1, blockIdx.y * 128, blockIdx.x * 128, su);
    else if (z == 1) gemm_body(h_k,  h_wk, bk, outK,  1, blockIdx.y * 128, blockIdx.x * 128, su);
    else             gemm_body(h_wv, h_v,  bv, outVt, 2, blockIdx.x * 128, blockIdx.y * 128, su);
}

// Output projection: fp16 AO in, fp32 out.
__global__ void __launch_bounds__(256, 2) gemm_out(
    const float* __restrict__ bias, float* __restrict__ C)
{
    extern __shared__ uint32_t su[];
    gemm_body((const __half*)g_AOh, h_wo, bias, C, 0, blockIdx.y * 128, blockIdx.x * 128, su);
}

// ---------------------------------------------------------------------------
// Flash attention, fp16 mma.m16n8k16 (R9 structure, proven). AO out in fp16.
// ---------------------------------------------------------------------------
#define QP 36
#define KP 36
#define VP 36
#define PP 36
#define ATTN_SMEM ((128*QP + 64*KP + 64*VP + 128*PP) * 4)

__global__ void __launch_bounds__(256) attn_kernel(const int* __restrict__ mask)
{
    extern __shared__ uint32_t su[];
    uint32_t* Qp = su;
    uint32_t* Kp = Qp + 128 * QP;
    uint32_t* Vp = Kp + 64 * KP;
    uint32_t* Pp = Vp + 64 * VP;

    const int tid  = threadIdx.x;
    const int w    = tid >> 5;
    const int lane = tid & 31;
    const int quad = lane >> 2;
    const int qt   = lane & 3;
    const int bh   = blockIdx.y;
    const int b    = bh >> 4;
    const int h    = bh & 15;
    const int q0   = blockIdx.x * 128;
    const int r0   = w * 16 + quad;

    const uint32_t* Qg = g_Qh  + ((size_t)bh * SEQ + q0) * (DK/2);
    const uint32_t* Kg = g_Kh  + (size_t)bh * SEQ * (DK/2);
    const uint32_t* Vg = g_Vth + (size_t)bh * DK * (SEQ/2);
    const int*      Mb = mask + (size_t)b * SEQ * SEQ;

#pragma unroll
    for (int t = 0; t < 8; t++) {
        int f = tid + t * 256, row = f >> 4, c2 = (f & 15) * 2;
        *(uint2*)(Qp + row * QP + c2) = *(const uint2*)(Qg + (size_t)row * (DK/2) + c2);
    }

    float oacc[8][4];
#pragma unroll
    for (int nf = 0; nf < 8; nf++)
#pragma unroll
        for (int j = 0; j < 4; j++) oacc[nf][j] = 0.f;
    float mi[2] = {-INFINITY, -INFINITY};
    float li[2] = {0.f, 0.f};

    for (int kt = 0; kt < SEQ; kt += 64) {
#pragma unroll
        for (int t = 0; t < 4; t++) {
            int f = tid + t * 256, row = f >> 4, c2 = (f & 15) * 2;
            *(uint2*)(Kp + row * KP + c2) =
                *(const uint2*)(Kg + (size_t)(kt + row) * (DK/2) + c2);
            *(uint2*)(Vp + row * VP + c2) =
                *(const uint2*)(Vg + (size_t)row * (SEQ/2) + (kt >> 1) + c2);
        }
        __syncthreads();

        float sacc[8][4];
#pragma unroll
        for (int nf = 0; nf < 8; nf++)
#pragma unroll
            for (int j = 0; j < 4; j++) sacc[nf][j] = 0.f;

#pragma unroll
        for (int kd = 0; kd < 4; kd++) {
            uint32_t a[4];
            const uint32_t* ap = Qp + r0 * QP + kd * 8 + qt;
            a[0] = ap[0];
            a[1] = ap[8 * QP];
            a[2] = ap[4];
            a[3] = ap[8 * QP + 4];
#pragma unroll
            for (int nf = 0; nf < 8; nf++) {
                uint32_t bfr[2];
                const uint32_t* bp = Kp + (nf * 8 + quad) * KP + kd * 8 + qt;
                bfr[0] = bp[0];
                bfr[1] = bp[4];
                mma_f16(sacc[nf], a, bfr);
            }
        }

#pragma unroll
        for (int r = 0; r < 2; r++) {
            const int qr = q0 + r0 + r * 8;
            const int* mrow = Mb + (size_t)qr * SEQ + kt;
            float p[16];
            float mx = -INFINITY;
#pragma unroll
            for (int nf = 0; nf < 8; nf++) {
                int2 mv = *(const int2*)(mrow + nf * 8 + qt * 2);
                float s0 = mv.x ? sacc[nf][2 * r]     * 0.125f : -INFINITY;
                float s1 = mv.y ? sacc[nf][2 * r + 1] * 0.125f : -INFINITY;
                p[2 * nf]     = s0;
                p[2 * nf + 1] = s1;
                mx = fmaxf(mx, fmaxf(s0, s1));
            }
            mx = fmaxf(mx, __shfl_xor_sync(0xffffffffu, mx, 1));
            mx = fmaxf(mx, __shfl_xor_sync(0xffffffffu, mx, 2));
            const float mnew = fmaxf(mi[r], mx);
            const float al   = __expf(mi[r] - mnew);
            float rs = 0.f;
            uint32_t* prow = Pp + (size_t)(r0 + 8 * r) * PP;
#pragma unroll
            for (int nf = 0; nf < 8; nf++) {
                float e0 = __expf(p[2 * nf]     - mnew);
                float e1 = __expf(p[2 * nf + 1] - mnew);
                rs += e0 + e1;
                prow[nf * 4 + qt] = pk2(e0, e1);
            }
            rs += __shfl_xor_sync(0xffffffffu, rs, 1);
            rs += __shfl_xor_sync(0xffffffffu, rs, 2);
            li[r] = li[r] * al + rs;
            mi[r] = mnew;
#pragma unroll
            for (int nf = 0; nf < 8; nf++) {
                oacc[nf][2 * r]     *= al;
                oacc[nf][2 * r + 1] *= al;
            }
        }
        __syncwarp();

#pragma unroll
        for (int kk = 0; kk < 4; kk++) {
            uint32_t a[4];
            const uint32_t* ap = Pp + r0 * PP + kk * 8 + qt;
            a[0] = ap[0];
            a[1] = ap[8 * PP];
            a[2] = ap[4];
            a[3] = ap[8 * PP + 4];
#pragma unroll
            for (int nf = 0; nf < 8; nf++) {
                uint32_t bfr[2];
                const uint32_t* bp = Vp + (nf * 8 + quad) * VP + kk * 8 + qt;
                bfr[0] = bp[0];
                bfr[1] = bp[4];
                mma_f16(oacc[nf], a, bfr);
            }
        }
        __syncthreads();
    }

    // Epilogue: fp16 pairs into g_AOh
#pragma unroll
    for (int r = 0; r < 2; r++) {
        const int qr = q0 + r0 + 8 * r;
        const float inv = 1.f / li[r];
        uint32_t* dst = g_AOh + (size_t)(b * SEQ + qr) * (D_MODEL/2) + h * (DK/2);
#pragma unroll
        for (int nf = 0; nf < 8; nf++)
            dst[nf * 4 + qt] = pk2(oacc[nf][2 * r] * inv, oacc[nf][2 * r + 1] * inv);
    }
}

// ---------------------------------------------------------------------------
extern "C" void kernel_launch(void* const* d_in, const int* in_sizes, int n_in,
                              void* d_out, int out_size)
{
    const float* q   = (const float*)d_in[0];
    const float* k   = (const float*)d_in[1];
    const float* v   = (const float*)d_in[2];
    const int*   msk = (const int*)  d_in[3];
    const float* b_q = (const float*)d_in[5];
    const float* b_k = (const float*)d_in[7];
    const float* b_v = (const float*)d_in[9];
    const float* b_o = (const float*)d_in[11];
    float* out = (float*)d_out;

    void *hq, *hk, *hv, *hwq, *hwk, *hwv, *hwo, *gQ, *gK, *gVt;
    cudaGetSymbolAddress(&hq,  h_q);
    cudaGetSymbolAddress(&hk,  h_k);
    cudaGetSymbolAddress(&hv,  h_v);
    cudaGetSymbolAddress(&hwq, h_wq);
    cudaGetSymbolAddress(&hwk, h_wk);
    cudaGetSymbolAddress(&hwv, h_wv);
    cudaGetSymbolAddress(&hwo, h_wo);
    cudaGetSymbolAddress(&gQ,  g_Qh);
    cudaGetSymbolAddress(&gK,  g_Kh);
    cudaGetSymbolAddress(&gVt, g_Vth);

    cudaFuncSetAttribute(gemm_qkv,   cudaFuncAttributeMaxDynamicSharedMemorySize, GEMM_SMEM);
    cudaFuncSetAttribute(gemm_out,   cudaFuncAttributeMaxDynamicSharedMemorySize, GEMM_SMEM);
    cudaFuncSetAttribute(attn_kernel, cudaFuncAttributeMaxDynamicSharedMemorySize, ATTN_SMEM);

    // fp16 pre-pass
    const int ACT4 = M_TOT * D_MODEL / 4;      // 1M float4
    const int W4   = D_MODEL * D_MODEL / 4;    // 256K float4
    to_half<<<ACT4 / 256, 256>>>((const float4*)q, (uint2*)hq, ACT4);
    to_half<<<ACT4 / 256, 256>>>((const float4*)k, (uint2*)hk, ACT4);
    to_half<<<ACT4 / 256, 256>>>((const float4*)v, (uint2*)hv, ACT4);
    to_half<<<W4 / 256, 256>>>((const float4*)d_in[4],  (uint2*)hwq, W4);
    to_half<<<W4 / 256, 256>>>((const float4*)d_in[6],  (uint2*)hwk, W4);
    to_half<<<W4 / 256, 256>>>((const float4*)d_in[8],  (uint2*)hwv, W4);
    to_half<<<W4 / 256, 256>>>((const float4*)d_in[10], (uint2*)hwo, W4);

    dim3 qkvgrid(8, 32, 3);
    gemm_qkv<<<qkvgrid, 256, GEMM_SMEM>>>((uint32_t*)gQ, (uint32_t*)gK, (uint32_t*)gVt,
                                          b_q, b_k, b_v);

    dim3 agrid(SEQ / 128, BATCH * NHEAD);     // (16, 32)
    attn_kernel<<<agrid, 256, ATTN_SMEM>>>(msk);

    dim3 ogrid(8, 32);
    gemm_out<<<ogrid, 256, GEMM_SMEM>>>(b_o, out);
}

// round 13
// speedup vs baseline: 9.2696x; 1.0879x over previous
#include <cuda_runtime.h>
#include <cuda_fp16.h>
#include <math.h>
#include <stdint.h>

#define D_MODEL 1024
#define NHEAD   16
#define DK      64
#define BATCH   2
#define SEQ     2048
#define M_TOT   (BATCH*SEQ)   // 4096

// fp16 copies of inputs (pre-pass)
__device__ __half h_q [M_TOT*D_MODEL];
__device__ __half h_k [M_TOT*D_MODEL];
__device__ __half h_v [M_TOT*D_MODEL];
__device__ __half h_wq[D_MODEL*D_MODEL];
__device__ __half h_wk[D_MODEL*D_MODEL];
__device__ __half h_wv[D_MODEL*D_MODEL];
__device__ __half h_wo[D_MODEL*D_MODEL];
// intermediates (fp16 pairs as uint32)
__device__ uint32_t g_Qh [BATCH*NHEAD*SEQ*(DK/2)];   // [bh][s][32 pairs(d)]
__device__ uint32_t g_Kh [BATCH*NHEAD*SEQ*(DK/2)];   // [bh][s][32 pairs(d)]
__device__ uint32_t g_Vth[BATCH*NHEAD*DK*(SEQ/2)];   // [bh][d][1024 pairs(s)]
__device__ uint32_t g_AOh[M_TOT*(D_MODEL/2)];        // attention out, fp16 pairs
__device__ uint32_t g_Mb [BATCH*SEQ*(SEQ/32)];       // mask bitwords [b][s][64]

// ---------------------------------------------------------------------------
__device__ __forceinline__ uint32_t pk2(float a, float b) {
    __half2 h = __floats2half2_rn(a, b);
    return *(uint32_t*)&h;
}
__device__ __forceinline__ uint32_t smem_u32(const void* p) {
    uint32_t a;
    asm("{ .reg .u64 t; cvta.to.shared.u64 t, %1; cvt.u32.u64 %0, t; }" : "=r"(a) : "l"(p));
    return a;
}
__device__ __forceinline__ void mma_f16(float* d, const uint32_t* a, const uint32_t* b) {
    asm volatile(
        "mma.sync.aligned.m16n8k16.row.col.f32.f16.f16.f32 "
        "{%0,%1,%2,%3}, {%4,%5,%6,%7}, {%8,%9}, {%0,%1,%2,%3};"
        : "+f"(d[0]), "+f"(d[1]), "+f"(d[2]), "+f"(d[3])
        : "r"(a[0]), "r"(a[1]), "r"(a[2]), "r"(a[3]), "r"(b[0]), "r"(b[1]));
}
#define CP16(dst, src) \
    asm volatile("cp.async.cg.shared.global [%0], [%1], 16;" :: "r"(dst), "l"(src))
#define CP_COMMIT() asm volatile("cp.async.commit_group;" ::: "memory")
#define CP_WAIT(n)  asm volatile("cp.async.wait_group %0;" :: "n"(n) : "memory")

// ---------------------------------------------------------------------------
// Pre-pass kernels
// ---------------------------------------------------------------------------
__global__ void to_half(const float4* __restrict__ src, uint2* __restrict__ dst, int n4) {
    int i = blockIdx.x * blockDim.x + threadIdx.x;
    if (i < n4) {
        float4 v = src[i];
        dst[i] = make_uint2(pk2(v.x, v.y), pk2(v.z, v.w));
    }
}
// mask int32 -> bitwords: word wi covers mask[wi*32 .. wi*32+31]
__global__ void mask_bits(const int* __restrict__ mask, uint32_t* __restrict__ bits) {
    int wi   = blockIdx.x * 8 + (threadIdx.x >> 5);
    int lane = threadIdx.x & 31;
    int v = mask[(size_t)wi * 32 + lane];
    uint32_t b = __ballot_sync(0xffffffffu, v != 0);
    if (lane == 0) bits[wi] = b;
}

// ---------------------------------------------------------------------------
// fp16 cp.async GEMM body (proven R10): C = A[M,1024] @ W[1024,1024]^T + bias
// ---------------------------------------------------------------------------
#define GP 20
#define NSTG 4
#define STG_U32 (2 * 128 * GP)
#define GEMM_SMEM (NSTG * STG_U32 * 4)   // 81920 B

__device__ __forceinline__ void gemm_issue(
    const __half* __restrict__ A, const __half* __restrict__ W,
    int m0, int n0, int k0, uint32_t sbase, int st)
{
    const int tid = threadIdx.x;
    const uint32_t abuf = sbase + (st * STG_U32) * 4;
    const uint32_t bbuf = abuf + 128 * GP * 4;
#pragma unroll
    for (int t = 0; t < 2; t++) {
        int c   = tid + t * 256;
        int row = c >> 2;
        int seg = c & 3;
        CP16(abuf + (row * GP + seg * 4) * 4, A + (size_t)(m0 + row) * 1024 + k0 + seg * 8);
        CP16(bbuf + (row * GP + seg * 4) * 4, W + (size_t)(n0 + row) * 1024 + k0 + seg * 8);
    }
}

__device__ __forceinline__ void gemm_body(
    const __half* __restrict__ A, const __half* __restrict__ W,
    const float* __restrict__ bias, void* __restrict__ C,
    int mode, int m0, int n0, uint32_t* su)
{
    const uint32_t sbase = smem_u32(su);
    const int tid  = threadIdx.x;
    const int wid  = tid >> 5;
    const int lane = tid & 31;
    const int quad = lane >> 2;
    const int qt   = lane & 3;
    const int wm   = wid >> 2;
    const int wn   = wid & 3;

    float acc[4][4][4];
#pragma unroll
    for (int mf = 0; mf < 4; mf++)
#pragma unroll
        for (int nf = 0; nf < 4; nf++)
#pragma unroll
            for (int j = 0; j < 4; j++) acc[mf][nf][j] = 0.f;

#pragma unroll
    for (int i = 0; i < NSTG - 1; i++) {
        gemm_issue(A, W, m0, n0, i * 32, sbase, i);
        CP_COMMIT();
    }

    for (int s = 0; s < 32; s++) {
        __syncthreads();      // all warps done computing stage s-1 (buffer reuse safe)
        if (s + NSTG - 1 < 32)
            gemm_issue(A, W, m0, n0, (s + NSTG - 1) * 32, sbase, (s + NSTG - 1) % NSTG);
        CP_COMMIT();
        CP_WAIT(NSTG - 1);
        __syncthreads();      // stage s visible to all threads

        const uint32_t* Au = su + (s % NSTG) * STG_U32;
        const uint32_t* Bu = Au + 128 * GP;
#pragma unroll
        for (int kd = 0; kd < 2; kd++) {
            uint32_t af[4][4];
#pragma unroll
            for (int mf = 0; mf < 4; mf++) {
                const uint32_t* ap = Au + (wm * 64 + mf * 16 + quad) * GP + kd * 8 + qt;
                af[mf][0] = ap[0];
                af[mf][1] = ap[8 * GP];
                af[mf][2] = ap[4];
                af[mf][3] = ap[8 * GP + 4];
            }
            uint32_t bf[4][2];
#pragma unroll
            for (int nf = 0; nf < 4; nf++) {
                const uint32_t* bp = Bu + (wn * 32 + nf * 8 + quad) * GP + kd * 8 + qt;
                bf[nf][0] = bp[0];
                bf[nf][1] = bp[4];
            }
#pragma unroll
            for (int mf = 0; mf < 4; mf++)
#pragma unroll
                for (int nf = 0; nf < 4; nf++)
                    mma_f16(acc[mf][nf], af[mf], bf[nf]);
        }
    }

#pragma unroll
    for (int mf = 0; mf < 4; mf++) {
#pragma unroll
        for (int nf = 0; nf < 4; nf++) {
            const int col = n0 + wn * 32 + nf * 8 + qt * 2;
#pragma unroll
            for (int jr = 0; jr < 2; jr++) {
                const int m = m0 + wm * 64 + mf * 16 + quad + 8 * jr;
                float v0 = acc[mf][nf][2 * jr];
                float v1 = acc[mf][nf][2 * jr + 1];
                if (mode == 0) {
                    v0 += bias[col]; v1 += bias[col + 1];
                    *(float2*)((float*)C + (size_t)m * D_MODEL + col) = make_float2(v0, v1);
                } else if (mode == 1) {
                    v0 += bias[col]; v1 += bias[col + 1];
                    const int bb = m >> 11, sq = m & (SEQ - 1);
                    const int h = col >> 6, pairp = (col & 63) >> 1;
                    ((uint32_t*)C)[((size_t)(bb * NHEAD + h) * SEQ + sq) * (DK/2) + pairp] = pk2(v0, v1);
                } else {
                    const float bv = bias[m];
                    v0 += bv; v1 += bv;
                    const int bb = col >> 11, sq = col & (SEQ - 1);
                    const int h = m >> 6, dk = m & (DK - 1);
                    ((uint32_t*)C)[((size_t)(bb * NHEAD + h) * DK + dk) * (SEQ/2) + (sq >> 1)] = pk2(v0, v1);
                }
            }
        }
    }
}

__global__ void __launch_bounds__(256, 2) gemm_qkv(
    uint32_t* outQ, uint32_t* outK, uint32_t* outVt,
    const float* __restrict__ bq, const float* __restrict__ bk, const float* __restrict__ bv)
{
    extern __shared__ uint32_t su[];
    const int z = blockIdx.z;
    if (z == 0)      gemm_body(h_q,  h_wq, bq, outQ,  1, blockIdx.y * 128, blockIdx.x * 128, su);
    else if (z == 1) gemm_body(h_k,  h_wk, bk, outK,  1, blockIdx.y * 128, blockIdx.x * 128, su);
    else             gemm_body(h_wv, h_v,  bv, outVt, 2, blockIdx.x * 128, blockIdx.y * 128, su);
}

__global__ void __launch_bounds__(256, 2) gemm_out(
    const float* __restrict__ bias, float* __restrict__ C)
{
    extern __shared__ uint32_t su[];
    gemm_body((const __half*)g_AOh, h_wo, bias, C, 0, blockIdx.y * 128, blockIdx.x * 128, su);
}

// ---------------------------------------------------------------------------
// Flash attention, fp16 mma.m16n8k16, cp.async double-buffered K/V (FIXED:
// GEMM-style two-barrier pipeline), bitmask mask. CTA: 128 q x one (b,h).
// ---------------------------------------------------------------------------
#define QP 36
#define KP 36
#define VP 36
#define PP 36
#define ATTN_SMEM ((128*QP + 2*64*KP + 2*64*VP + 128*PP) * 4)   // 73728 B

__device__ __forceinline__ void attn_issue(
    const uint32_t* __restrict__ Kg, const uint32_t* __restrict__ Vg,
    int kt, uint32_t kbase, uint32_t vbase)
{
    const int tid = threadIdx.x;
#pragma unroll
    for (int t = 0; t < 2; t++) {
        int f   = tid + t * 256;    // 0..511 : 64 rows x 8 segments
        int row = f >> 3;
        int seg = f & 7;
        CP16(kbase + (row * KP + seg * 4) * 4,
             Kg + (size_t)(kt + row) * (DK/2) + seg * 4);
        CP16(vbase + (row * VP + seg * 4) * 4,
             Vg + (size_t)row * (SEQ/2) + (kt >> 1) + seg * 4);
    }
}

__global__ void __launch_bounds__(256, 2) attn_kernel()
{
    extern __shared__ uint32_t su[];
    uint32_t* Qp  = su;                       // [128][QP]
    uint32_t* Kp0 = Qp + 128 * QP;            // [64][KP] x2 stages
    uint32_t* Vp0 = Kp0 + 2 * 64 * KP;        // [64][VP] x2 stages
    uint32_t* Pp  = Vp0 + 2 * 64 * VP;        // [128][PP]
    const uint32_t kb = smem_u32(Kp0);
    const uint32_t vb = smem_u32(Vp0);

    const int tid  = threadIdx.x;
    const int w    = tid >> 5;
    const int lane = tid & 31;
    const int quad = lane >> 2;
    const int qt   = lane & 3;
    const int bh   = blockIdx.y;
    const int b    = bh >> 4;
    const int h    = bh & 15;
    const int q0   = blockIdx.x * 128;
    const int r0   = w * 16 + quad;

    const uint32_t* Qg = g_Qh  + ((size_t)bh * SEQ + q0) * (DK/2);
    const uint32_t* Kg = g_Kh  + (size_t)bh * SEQ * (DK/2);
    const uint32_t* Vg = g_Vth + (size_t)bh * DK * (SEQ/2);

    // Prologue: issue tile 0, then stage Q while it flies.
    attn_issue(Kg, Vg, 0, kb, vb);
    CP_COMMIT();

#pragma unroll
    for (int t = 0; t < 8; t++) {
        int f = tid + t * 256, row = f >> 4, c2 = (f & 15) * 2;
        *(uint2*)(Qp + row * QP + c2) = *(const uint2*)(Qg + (size_t)row * (DK/2) + c2);
    }

    float oacc[8][4];
#pragma unroll
    for (int nf = 0; nf < 8; nf++)
#pragma unroll
        for (int j = 0; j < 4; j++) oacc[nf][j] = 0.f;
    float mi[2] = {-INFINITY, -INFINITY};
    float li[2] = {0.f, 0.f};

    for (int t = 0; t < 32; t++) {
        const int st = t & 1;
        const int kt = t * 64;

        __syncthreads();   // ALL warps done with tile t-1 -> stage st^1 is free
        if (t + 1 < 32)
            attn_issue(Kg, Vg, kt + 64, kb + (st ^ 1) * 64 * KP * 4,
                                         vb + (st ^ 1) * 64 * VP * 4);
        CP_COMMIT();       // unconditional: keeps group count exact at tail
        CP_WAIT(1);        // tile t's group complete
        __syncthreads();   // tile t visible to all warps

        const uint32_t* Kc = Kp0 + st * 64 * KP;
        const uint32_t* Vc = Vp0 + st * 64 * VP;

        // ---- QK^T ----
        float sacc[8][4];
#pragma unroll
        for (int nf = 0; nf < 8; nf++)
#pragma unroll
            for (int j = 0; j < 4; j++) sacc[nf][j] = 0.f;

#pragma unroll
        for (int kd = 0; kd < 4; kd++) {
            uint32_t a[4];
            const uint32_t* ap = Qp + r0 * QP + kd * 8 + qt;
            a[0] = ap[0];
            a[1] = ap[8 * QP];
            a[2] = ap[4];
            a[3] = ap[8 * QP + 4];
#pragma unroll
            for (int nf = 0; nf < 8; nf++) {
                uint32_t bfr[2];
                const uint32_t* bp = Kc + (nf * 8 + quad) * KP + kd * 8 + qt;
                bfr[0] = bp[0];
                bfr[1] = bp[4];
                mma_f16(sacc[nf], a, bfr);
            }
        }

        // ---- bitmask + online softmax ----
#pragma unroll
        for (int r = 0; r < 2; r++) {
            const int qr = q0 + r0 + r * 8;
            uint2 mw = *(const uint2*)(g_Mb + ((size_t)b * SEQ + qr) * (SEQ/32) + (kt >> 5));
            float p[16];
            float mx = -INFINITY;
#pragma unroll
            for (int nf = 0; nf < 8; nf++) {
                const uint32_t wsel = (nf < 4) ? mw.x : mw.y;
                const int bit = (nf * 8 + qt * 2) & 31;
                float s0 = ((wsel >> bit) & 1u)       ? sacc[nf][2 * r]     * 0.125f : -INFINITY;
                float s1 = ((wsel >> (bit + 1)) & 1u) ? sacc[nf][2 * r + 1] * 0.125f : -INFINITY;
                p[2 * nf]     = s0;
                p[2 * nf + 1] = s1;
                mx = fmaxf(mx, fmaxf(s0, s1));
            }
            mx = fmaxf(mx, __shfl_xor_sync(0xffffffffu, mx, 1));
            mx = fmaxf(mx, __shfl_xor_sync(0xffffffffu, mx, 2));
            const float mnew = fmaxf(mi[r], mx);
            const float al   = __expf(mi[r] - mnew);
            float rs = 0.f;
            uint32_t* prow = Pp + (size_t)(r0 + 8 * r) * PP;
#pragma unroll
            for (int nf = 0; nf < 8; nf++) {
                float e0 = __expf(p[2 * nf]     - mnew);
                float e1 = __expf(p[2 * nf + 1] - mnew);
                rs += e0 + e1;
                prow[nf * 4 + qt] = pk2(e0, e1);
            }
            rs += __shfl_xor_sync(0xffffffffu, rs, 1);
            rs += __shfl_xor_sync(0xffffffffu, rs, 2);
            li[r] = li[r] * al + rs;
            mi[r] = mnew;
#pragma unroll
            for (int nf = 0; nf < 8; nf++) {
                oacc[nf][2 * r]     *= al;
                oacc[nf][2 * r + 1] *= al;
            }
        }
        __syncwarp();   // P written/read by this warp only

        // ---- PV ----
#pragma unroll
        for (int kk = 0; kk < 4; kk++) {
            uint32_t a[4];
            const uint32_t* ap = Pp + r0 * PP + kk * 8 + qt;
            a[0] = ap[0];
            a[1] = ap[8 * PP];
            a[2] = ap[4];
            a[3] = ap[8 * PP + 4];
#pragma unroll
            for (int nf = 0; nf < 8; nf++) {
                uint32_t bfr[2];
                const uint32_t* bp = Vc + (nf * 8 + quad) * VP + kk * 8 + qt;
                bfr[0] = bp[0];
                bfr[1] = bp[4];
                mma_f16(oacc[nf], a, bfr);
            }
        }
    }

    // Epilogue: fp16 pairs into g_AOh
#pragma unroll
    for (int r = 0; r < 2; r++) {
        const int qr = q0 + r0 + 8 * r;
        const float inv = 1.f / li[r];
        uint32_t* dst = g_AOh + (size_t)(b * SEQ + qr) * (D_MODEL/2) + h * (DK/2);
#pragma unroll
        for (int nf = 0; nf < 8; nf++)
            dst[nf * 4 + qt] = pk2(oacc[nf][2 * r] * inv, oacc[nf][2 * r + 1] * inv);
    }
}

// ---------------------------------------------------------------------------
extern "C" void kernel_launch(void* const* d_in, const int* in_sizes, int n_in,
                              void* d_out, int out_size)
{
    const float* q   = (const float*)d_in[0];
    const float* k   = (const float*)d_in[1];
    const float* v   = (const float*)d_in[2];
    const int*   msk = (const int*)  d_in[3];
    const float* b_q = (const float*)d_in[5];
    const float* b_k = (const float*)d_in[7];
    const float* b_v = (const float*)d_in[9];
    const float* b_o = (const float*)d_in[11];
    float* out = (float*)d_out;

    void *hq, *hk, *hv, *hwq, *hwk, *hwv, *hwo, *gQ, *gK, *gVt, *gMb;
    cudaGetSymbolAddress(&hq,  h_q);
    cudaGetSymbolAddress(&hk,  h_k);
    cudaGetSymbolAddress(&hv,  h_v);
    cudaGetSymbolAddress(&hwq, h_wq);
    cudaGetSymbolAddress(&hwk, h_wk);
    cudaGetSymbolAddress(&hwv, h_wv);
    cudaGetSymbolAddress(&hwo, h_wo);
    cudaGetSymbolAddress(&gQ,  g_Qh);
    cudaGetSymbolAddress(&gK,  g_Kh);
    cudaGetSymbolAddress(&gVt, g_Vth);
    cudaGetSymbolAddress(&gMb, g_Mb);

    cudaFuncSetAttribute(gemm_qkv,    cudaFuncAttributeMaxDynamicSharedMemorySize, GEMM_SMEM);
    cudaFuncSetAttribute(gemm_out,    cudaFuncAttributeMaxDynamicSharedMemorySize, GEMM_SMEM);
    cudaFuncSetAttribute(attn_kernel, cudaFuncAttributeMaxDynamicSharedMemorySize, ATTN_SMEM);

    // fp16 + bitmask pre-pass
    const int ACT4 = M_TOT * D_MODEL / 4;
    const int W4   = D_MODEL * D_MODEL / 4;
    to_half<<<ACT4 / 256, 256>>>((const float4*)q, (uint2*)hq, ACT4);
    to_half<<<ACT4 / 256, 256>>>((const float4*)k, (uint2*)hk, ACT4);
    to_half<<<ACT4 / 256, 256>>>((const float4*)v, (uint2*)hv, ACT4);
    to_half<<<W4 / 256, 256>>>((const float4*)d_in[4],  (uint2*)hwq, W4);
    to_half<<<W4 / 256, 256>>>((const float4*)d_in[6],  (uint2*)hwk, W4);
    to_half<<<W4 / 256, 256>>>((const float4*)d_in[8],  (uint2*)hwv, W4);
    to_half<<<W4 / 256, 256>>>((const float4*)d_in[10], (uint2*)hwo, W4);
    mask_bits<<<BATCH * SEQ * (SEQ/32) / 8, 256>>>(msk, (uint32_t*)gMb);

    dim3 qkvgrid(8, 32, 3);
    gemm_qkv<<<qkvgrid, 256, GEMM_SMEM>>>((uint32_t*)gQ, (uint32_t*)gK, (uint32_t*)gVt,
                                          b_q, b_k, b_v);

    dim3 agrid(SEQ / 128, BATCH * NHEAD);
    attn_kernel<<<agrid, 256, ATTN_SMEM>>>();

    dim3 ogrid(8, 32);
    gemm_out<<<ogrid, 256, GEMM_SMEM>>>(b_o, out);
}

// round 14
// speedup vs baseline: 9.9537x; 1.0738x over previous
#include <cuda_runtime.h>
#include <cuda_fp16.h>
#include <math.h>
#include <stdint.h>

#define D_MODEL 1024
#define NHEAD   16
#define DK      64
#define BATCH   2
#define SEQ     2048
#define M_TOT   (BATCH*SEQ)   // 4096

// fp16 copies of inputs (pre-pass)
__device__ __half h_q [M_TOT*D_MODEL];
__device__ __half h_k [M_TOT*D_MODEL];
__device__ __half h_v [M_TOT*D_MODEL];
__device__ __half h_wq[D_MODEL*D_MODEL];
__device__ __half h_wk[D_MODEL*D_MODEL];
__device__ __half h_wv[D_MODEL*D_MODEL];
__device__ __half h_wo[D_MODEL*D_MODEL];
// intermediates (fp16 pairs as uint32)
__device__ uint32_t g_Qh [BATCH*NHEAD*SEQ*(DK/2)];   // [bh][s][32 pairs(d)] (pre-scaled by 1/8)
__device__ uint32_t g_Kh [BATCH*NHEAD*SEQ*(DK/2)];   // [bh][s][32 pairs(d)]
__device__ uint32_t g_Vth[BATCH*NHEAD*DK*(SEQ/2)];   // [bh][d][1024 pairs(s)]
__device__ uint32_t g_AOh[M_TOT*(D_MODEL/2)];        // attention out, fp16 pairs
__device__ uint32_t g_Mb [BATCH*SEQ*(SEQ/32)];       // mask bitwords [b][s][64]

// ---------------------------------------------------------------------------
__device__ __forceinline__ uint32_t pk2(float a, float b) {
    __half2 h = __floats2half2_rn(a, b);
    return *(uint32_t*)&h;
}
__device__ __forceinline__ uint32_t smem_u32(const void* p) {
    uint32_t a;
    asm("{ .reg .u64 t; cvta.to.shared.u64 t, %1; cvt.u32.u64 %0, t; }" : "=r"(a) : "l"(p));
    return a;
}
__device__ __forceinline__ void mma_f16(float* d, const uint32_t* a, const uint32_t* b) {
    asm volatile(
        "mma.sync.aligned.m16n8k16.row.col.f32.f16.f16.f32 "
        "{%0,%1,%2,%3}, {%4,%5,%6,%7}, {%8,%9}, {%0,%1,%2,%3};"
        : "+f"(d[0]), "+f"(d[1]), "+f"(d[2]), "+f"(d[3])
        : "r"(a[0]), "r"(a[1]), "r"(a[2]), "r"(a[3]), "r"(b[0]), "r"(b[1]));
}
#define CP16(dst, src) \
    asm volatile("cp.async.cg.shared.global [%0], [%1], 16;" :: "r"(dst), "l"(src))
#define CP_COMMIT() asm volatile("cp.async.commit_group;" ::: "memory")
#define CP_WAIT(n)  asm volatile("cp.async.wait_group %0;" :: "n"(n) : "memory")

// ---------------------------------------------------------------------------
// Pre-pass kernels (fused via blockIdx.z)
// ---------------------------------------------------------------------------
__global__ void to_half_acts(const float4* __restrict__ a, const float4* __restrict__ b,
                             const float4* __restrict__ c,
                             uint2* __restrict__ da, uint2* __restrict__ db,
                             uint2* __restrict__ dc) {
    int i = blockIdx.x * blockDim.x + threadIdx.x;
    const float4* s = (blockIdx.z == 0) ? a : (blockIdx.z == 1) ? b : c;
    uint2*        d = (blockIdx.z == 0) ? da : (blockIdx.z == 1) ? db : dc;
    float4 v = s[i];
    d[i] = make_uint2(pk2(v.x, v.y), pk2(v.z, v.w));
}
__global__ void to_half_wts(const float4* __restrict__ a, const float4* __restrict__ b,
                            const float4* __restrict__ c, const float4* __restrict__ e,
                            uint2* __restrict__ da, uint2* __restrict__ db,
                            uint2* __restrict__ dc, uint2* __restrict__ de) {
    int i = blockIdx.x * blockDim.x + threadIdx.x;
    const float4* s = (blockIdx.z == 0) ? a : (blockIdx.z == 1) ? b :
                      (blockIdx.z == 2) ? c : e;
    uint2*        d = (blockIdx.z == 0) ? da : (blockIdx.z == 1) ? db :
                      (blockIdx.z == 2) ? dc : de;
    float4 v = s[i];
    d[i] = make_uint2(pk2(v.x, v.y), pk2(v.z, v.w));
}
__global__ void mask_bits(const int* __restrict__ mask, uint32_t* __restrict__ bits) {
    int wi   = blockIdx.x * 8 + (threadIdx.x >> 5);
    int lane = threadIdx.x & 31;
    int v = mask[(size_t)wi * 32 + lane];
    uint32_t b = __ballot_sync(0xffffffffu, v != 0);
    if (lane == 0) bits[wi] = b;
}

// ---------------------------------------------------------------------------
// fp16 cp.async GEMM body (proven): C = A[M,1024] @ W[1024,1024]^T + bias
// mode 0: fp32 row-major; mode 1: fp16 pairs head-split, output scaled by
// oscale; mode 2: fp16 pairs Vt layout (bias by row m)
// ---------------------------------------------------------------------------
#define GP 20
#define NSTG 4
#define STG_U32 (2 * 128 * GP)
#define GEMM_SMEM (NSTG * STG_U32 * 4)   // 81920 B

__device__ __forceinline__ void gemm_issue(
    const __half* __restrict__ A, const __half* __restrict__ W,
    int m0, int n0, int k0, uint32_t sbase, int st)
{
    const int tid = threadIdx.x;
    const uint32_t abuf = sbase + (st * STG_U32) * 4;
    const uint32_t bbuf = abuf + 128 * GP * 4;
#pragma unroll
    for (int t = 0; t < 2; t++) {
        int c   = tid + t * 256;
        int row = c >> 2;
        int seg = c & 3;
        CP16(abuf + (row * GP + seg * 4) * 4, A + (size_t)(m0 + row) * 1024 + k0 + seg * 8);
        CP16(bbuf + (row * GP + seg * 4) * 4, W + (size_t)(n0 + row) * 1024 + k0 + seg * 8);
    }
}

__device__ __forceinline__ void gemm_body(
    const __half* __restrict__ A, const __half* __restrict__ W,
    const float* __restrict__ bias, void* __restrict__ C,
    int mode, float oscale, int m0, int n0, uint32_t* su)
{
    const uint32_t sbase = smem_u32(su);
    const int tid  = threadIdx.x;
    const int wid  = tid >> 5;
    const int lane = tid & 31;
    const int quad = lane >> 2;
    const int qt   = lane & 3;
    const int wm   = wid >> 2;
    const int wn   = wid & 3;

    float acc[4][4][4];
#pragma unroll
    for (int mf = 0; mf < 4; mf++)
#pragma unroll
        for (int nf = 0; nf < 4; nf++)
#pragma unroll
            for (int j = 0; j < 4; j++) acc[mf][nf][j] = 0.f;

#pragma unroll
    for (int i = 0; i < NSTG - 1; i++) {
        gemm_issue(A, W, m0, n0, i * 32, sbase, i);
        CP_COMMIT();
    }

    for (int s = 0; s < 32; s++) {
        __syncthreads();
        if (s + NSTG - 1 < 32)
            gemm_issue(A, W, m0, n0, (s + NSTG - 1) * 32, sbase, (s + NSTG - 1) % NSTG);
        CP_COMMIT();
        CP_WAIT(NSTG - 1);
        __syncthreads();

        const uint32_t* Au = su + (s % NSTG) * STG_U32;
        const uint32_t* Bu = Au + 128 * GP;
#pragma unroll
        for (int kd = 0; kd < 2; kd++) {
            uint32_t af[4][4];
#pragma unroll
            for (int mf = 0; mf < 4; mf++) {
                const uint32_t* ap = Au + (wm * 64 + mf * 16 + quad) * GP + kd * 8 + qt;
                af[mf][0] = ap[0];
                af[mf][1] = ap[8 * GP];
                af[mf][2] = ap[4];
                af[mf][3] = ap[8 * GP + 4];
            }
            uint32_t bf[4][2];
#pragma unroll
            for (int nf = 0; nf < 4; nf++) {
                const uint32_t* bp = Bu + (wn * 32 + nf * 8 + quad) * GP + kd * 8 + qt;
                bf[nf][0] = bp[0];
                bf[nf][1] = bp[4];
            }
#pragma unroll
            for (int mf = 0; mf < 4; mf++)
#pragma unroll
                for (int nf = 0; nf < 4; nf++)
                    mma_f16(acc[mf][nf], af[mf], bf[nf]);
        }
    }

#pragma unroll
    for (int mf = 0; mf < 4; mf++) {
#pragma unroll
        for (int nf = 0; nf < 4; nf++) {
            const int col = n0 + wn * 32 + nf * 8 + qt * 2;
#pragma unroll
            for (int jr = 0; jr < 2; jr++) {
                const int m = m0 + wm * 64 + mf * 16 + quad + 8 * jr;
                float v0 = acc[mf][nf][2 * jr];
                float v1 = acc[mf][nf][2 * jr + 1];
                if (mode == 0) {
                    v0 += bias[col]; v1 += bias[col + 1];
                    *(float2*)((float*)C + (size_t)m * D_MODEL + col) = make_float2(v0, v1);
                } else if (mode == 1) {
                    v0 = (v0 + bias[col]) * oscale;
                    v1 = (v1 + bias[col + 1]) * oscale;
                    const int bb = m >> 11, sq = m & (SEQ - 1);
                    const int h = col >> 6, pairp = (col & 63) >> 1;
                    ((uint32_t*)C)[((size_t)(bb * NHEAD + h) * SEQ + sq) * (DK/2) + pairp] = pk2(v0, v1);
                } else {
                    const float bv = bias[m];
                    v0 += bv; v1 += bv;
                    const int bb = col >> 11, sq = col & (SEQ - 1);
                    const int h = m >> 6, dk = m & (DK - 1);
                    ((uint32_t*)C)[((size_t)(bb * NHEAD + h) * DK + dk) * (SEQ/2) + (sq >> 1)] = pk2(v0, v1);
                }
            }
        }
    }
}

__global__ void __launch_bounds__(256, 2) gemm_qkv(
    uint32_t* outQ, uint32_t* outK, uint32_t* outVt,
    const float* __restrict__ bq, const float* __restrict__ bk, const float* __restrict__ bv)
{
    extern __shared__ uint32_t su[];
    const int z = blockIdx.z;
    if (z == 0)      gemm_body(h_q,  h_wq, bq, outQ,  1, 0.125f, blockIdx.y * 128, blockIdx.x * 128, su);
    else if (z == 1) gemm_body(h_k,  h_wk, bk, outK,  1, 1.0f,   blockIdx.y * 128, blockIdx.x * 128, su);
    else             gemm_body(h_wv, h_v,  bv, outVt, 2, 1.0f,   blockIdx.x * 128, blockIdx.y * 128, su);
}

__global__ void __launch_bounds__(256, 2) gemm_out(
    const float* __restrict__ bias, float* __restrict__ C)
{
    extern __shared__ uint32_t su[];
    gemm_body((const __half*)g_AOh, h_wo, bias, C, 0, 1.0f, blockIdx.y * 128, blockIdx.x * 128, su);
}

// ---------------------------------------------------------------------------
// Flash attention, fp16 mma.m16n8k16. Register-resident P (C-frag == A-frag
// layout for fp16 pairs), hoisted Q fragments, 3-stage cp.async K/V pipeline,
// bitmask mask. CTA: 128 q x one (b,h), 8 warps, 2 CTAs/SM.
// ---------------------------------------------------------------------------
#define QP 36
#define KP 36
#define VP 36
#define ANST 3
#define ATTN_SMEM ((128*QP + ANST*64*KP + ANST*64*VP) * 4)   // 73728 B

__device__ __forceinline__ void attn_issue(
    const uint32_t* __restrict__ Kg, const uint32_t* __restrict__ Vg,
    int kt, uint32_t kbase, uint32_t vbase)
{
    const int tid = threadIdx.x;
#pragma unroll
    for (int t = 0; t < 2; t++) {
        int f   = tid + t * 256;    // 0..511 : 64 rows x 8 segments
        int row = f >> 3;
        int seg = f & 7;
        CP16(kbase + (row * KP + seg * 4) * 4,
             Kg + (size_t)(kt + row) * (DK/2) + seg * 4);
        CP16(vbase + (row * VP + seg * 4) * 4,
             Vg + (size_t)row * (SEQ/2) + (kt >> 1) + seg * 4);
    }
}

__global__ void __launch_bounds__(256, 2) attn_kernel()
{
    extern __shared__ uint32_t su[];
    uint32_t* Qp  = su;                        // [128][QP]
    uint32_t* Kp0 = Qp + 128 * QP;             // [64][KP] x3 stages
    uint32_t* Vp0 = Kp0 + ANST * 64 * KP;      // [64][VP] x3 stages
    const uint32_t kb = smem_u32(Kp0);
    const uint32_t vb = smem_u32(Vp0);

    const int tid  = threadIdx.x;
    const int w    = tid >> 5;
    const int lane = tid & 31;
    const int quad = lane >> 2;
    const int qt   = lane & 3;
    const int bh   = blockIdx.y;
    const int b    = bh >> 4;
    const int h    = bh & 15;
    const int q0   = blockIdx.x * 128;
    const int r0   = w * 16 + quad;

    const uint32_t* Qg = g_Qh  + ((size_t)bh * SEQ + q0) * (DK/2);
    const uint32_t* Kg = g_Kh  + (size_t)bh * SEQ * (DK/2);
    const uint32_t* Vg = g_Vth + (size_t)bh * DK * (SEQ/2);

    // Prologue: issue tiles 0 and 1, then stage Q.
    attn_issue(Kg, Vg, 0,  kb,                vb);
    CP_COMMIT();
    attn_issue(Kg, Vg, 64, kb + 64 * KP * 4,  vb + 64 * VP * 4);
    CP_COMMIT();

#pragma unroll
    for (int t = 0; t < 8; t++) {
        int f = tid + t * 256, row = f >> 4, c2 = (f & 15) * 2;
        *(uint2*)(Qp + row * QP + c2) = *(const uint2*)(Qg + (size_t)row * (DK/2) + c2);
    }
    __syncthreads();

    // Hoist loop-invariant Q fragments into registers.
    uint32_t qa[4][4];
#pragma unroll
    for (int kd = 0; kd < 4; kd++) {
        const uint32_t* ap = Qp + r0 * QP + kd * 8 + qt;
        qa[kd][0] = ap[0];
        qa[kd][1] = ap[8 * QP];
        qa[kd][2] = ap[4];
        qa[kd][3] = ap[8 * QP + 4];
    }

    float oacc[8][4];
#pragma unroll
    for (int nf = 0; nf < 8; nf++)
#pragma unroll
        for (int j = 0; j < 4; j++) oacc[nf][j] = 0.f;
    float mi[2] = {-INFINITY, -INFINITY};
    float li[2] = {0.f, 0.f};

    for (int t = 0; t < 32; t++) {
        const int st = t % ANST;
        const int kt = t * 64;

        __syncthreads();   // all warps done with tile t-1 -> its stage is free
        if (t + 2 < 32) {
            const int si = (t + 2) % ANST;
            attn_issue(Kg, Vg, kt + 128, kb + si * 64 * KP * 4,
                                          vb + si * 64 * VP * 4);
        }
        CP_COMMIT();       // unconditional: group count stays exact at tail
        CP_WAIT(2);        // tile t complete
        __syncthreads();   // visible to all warps

        const uint32_t* Kc = Kp0 + st * 64 * KP;
        const uint32_t* Vc = Vp0 + st * 64 * VP;

        // ---- QK^T (Q pre-scaled by 1/8) ----
        float sacc[8][4];
#pragma unroll
        for (int nf = 0; nf < 8; nf++)
#pragma unroll
            for (int j = 0; j < 4; j++) sacc[nf][j] = 0.f;

#pragma unroll
        for (int kd = 0; kd < 4; kd++) {
#pragma unroll
            for (int nf = 0; nf < 8; nf++) {
                uint32_t bfr[2];
                const uint32_t* bp = Kc + (nf * 8 + quad) * KP + kd * 8 + qt;
                bfr[0] = bp[0];
                bfr[1] = bp[4];
                mma_f16(sacc[nf], qa[kd], bfr);
            }
        }

        // ---- bitmask + online softmax; P packed straight into A-frags ----
        uint32_t pe[8][2];
#pragma unroll
        for (int r = 0; r < 2; r++) {
            const int qr = q0 + r0 + r * 8;
            uint2 mw = *(const uint2*)(g_Mb + ((size_t)b * SEQ + qr) * (SEQ/32) + (kt >> 5));
            float p[16];
            float mx = -INFINITY;
#pragma unroll
            for (int nf = 0; nf < 8; nf++) {
                const uint32_t wsel = (nf < 4) ? mw.x : mw.y;
                const int bit = (nf * 8 + qt * 2) & 31;
                float s0 = ((wsel >> bit) & 1u)       ? sacc[nf][2 * r]     : -INFINITY;
                float s1 = ((wsel >> (bit + 1)) & 1u) ? sacc[nf][2 * r + 1] : -INFINITY;
                p[2 * nf]     = s0;
                p[2 * nf + 1] = s1;
                mx = fmaxf(mx, fmaxf(s0, s1));
            }
            mx = fmaxf(mx, __shfl_xor_sync(0xffffffffu, mx, 1));
            mx = fmaxf(mx, __shfl_xor_sync(0xffffffffu, mx, 2));
            const float mnew = fmaxf(mi[r], mx);
            const float al   = __expf(mi[r] - mnew);
            float rs = 0.f;
#pragma unroll
            for (int nf = 0; nf < 8; nf++) {
                float e0 = __expf(p[2 * nf]     - mnew);
                float e1 = __expf(p[2 * nf + 1] - mnew);
                rs += e0 + e1;
                pe[nf][r] = pk2(e0, e1);
            }
            rs += __shfl_xor_sync(0xffffffffu, rs, 1);
            rs += __shfl_xor_sync(0xffffffffu, rs, 2);
            li[r] = li[r] * al + rs;
            mi[r] = mnew;
#pragma unroll
            for (int nf = 0; nf < 8; nf++) {
                oacc[nf][2 * r]     *= al;
                oacc[nf][2 * r + 1] *= al;
            }
        }

        // ---- PV: O += P @ V, P A-frags direct from registers ----
#pragma unroll
        for (int kk = 0; kk < 4; kk++) {
            uint32_t a[4];
            a[0] = pe[2 * kk][0];
            a[1] = pe[2 * kk][1];
            a[2] = pe[2 * kk + 1][0];
            a[3] = pe[2 * kk + 1][1];
#pragma unroll
            for (int nf = 0; nf < 8; nf++) {
                uint32_t bfr[2];
                const uint32_t* bp = Vc + (nf * 8 + quad) * VP + kk * 8 + qt;
                bfr[0] = bp[0];
                bfr[1] = bp[4];
                mma_f16(oacc[nf], a, bfr);
            }
        }
    }

    // Epilogue: fp16 pairs into g_AOh
#pragma unroll
    for (int r = 0; r < 2; r++) {
        const int qr = q0 + r0 + 8 * r;
        const float inv = 1.f / li[r];
        uint32_t* dst = g_AOh + (size_t)(b * SEQ + qr) * (D_MODEL/2) + h * (DK/2);
#pragma unroll
        for (int nf = 0; nf < 8; nf++)
            dst[nf * 4 + qt] = pk2(oacc[nf][2 * r] * inv, oacc[nf][2 * r + 1] * inv);
    }
}

// ---------------------------------------------------------------------------
extern "C" void kernel_launch(void* const* d_in, const int* in_sizes, int n_in,
                              void* d_out, int out_size)
{
    const float* q   = (const float*)d_in[0];
    const float* k   = (const float*)d_in[1];
    const float* v   = (const float*)d_in[2];
    const int*   msk = (const int*)  d_in[3];
    const float* b_q = (const float*)d_in[5];
    const float* b_k = (const float*)d_in[7];
    const float* b_v = (const float*)d_in[9];
    const float* b_o = (const float*)d_in[11];
    float* out = (float*)d_out;

    void *hq, *hk, *hv, *hwq, *hwk, *hwv, *hwo, *gQ, *gK, *gVt, *gMb;
    cudaGetSymbolAddress(&hq,  h_q);
    cudaGetSymbolAddress(&hk,  h_k);
    cudaGetSymbolAddress(&hv,  h_v);
    cudaGetSymbolAddress(&hwq, h_wq);
    cudaGetSymbolAddress(&hwk, h_wk);
    cudaGetSymbolAddress(&hwv, h_wv);
    cudaGetSymbolAddress(&hwo, h_wo);
    cudaGetSymbolAddress(&gQ,  g_Qh);
    cudaGetSymbolAddress(&gK,  g_Kh);
    cudaGetSymbolAddress(&gVt, g_Vth);
    cudaGetSymbolAddress(&gMb, g_Mb);

    cudaFuncSetAttribute(gemm_qkv,    cudaFuncAttributeMaxDynamicSharedMemorySize, GEMM_SMEM);
    cudaFuncSetAttribute(gemm_out,    cudaFuncAttributeMaxDynamicSharedMemorySize, GEMM_SMEM);
    cudaFuncSetAttribute(attn_kernel, cudaFuncAttributeMaxDynamicSharedMemorySize, ATTN_SMEM);

    // fp16 + bitmask pre-pass (fused)
    const int ACT4 = M_TOT * D_MODEL / 4;
    const int W4   = D_MODEL * D_MODEL / 4;
    dim3 agrid_h(ACT4 / 256, 1, 3);
    to_half_acts<<<agrid_h, 256>>>((const float4*)q, (const float4*)k, (const float4*)v,
                                   (uint2*)hq, (uint2*)hk, (uint2*)hv);
    dim3 wgrid_h(W4 / 256, 1, 4);
    to_half_wts<<<wgrid_h, 256>>>((const float4*)d_in[4], (const float4*)d_in[6],
                                  (const float4*)d_in[8], (const float4*)d_in[10],
                                  (uint2*)hwq, (uint2*)hwk, (uint2*)hwv, (uint2*)hwo);
    mask_bits<<<BATCH * SEQ * (SEQ/32) / 8, 256>>>(msk, (uint32_t*)gMb);

    dim3 qkvgrid(8, 32, 3);
    gemm_qkv<<<qkvgrid, 256, GEMM_SMEM>>>((uint32_t*)gQ, (uint32_t*)gK, (uint32_t*)gVt,
                                          b_q, b_k, b_v);

    dim3 agrid(SEQ / 128, BATCH * NHEAD);
    attn_kernel<<<agrid, 256, ATTN_SMEM>>>();

    dim3 ogrid(8, 32);
    gemm_out<<<ogrid, 256, GEMM_SMEM>>>(b_o, out);
}

// round 15
// speedup vs baseline: 10.0877x; 1.0135x over previous
#include <cuda_runtime.h>
#include <cuda_fp16.h>
#include <math.h>
#include <stdint.h>

#define D_MODEL 1024
#define NHEAD   16
#define DK      64
#define BATCH   2
#define SEQ     2048
#define M_TOT   (BATCH*SEQ)   // 4096

// fp16 copies of inputs (pre-pass)
__device__ __half h_q [M_TOT*D_MODEL];
__device__ __half h_k [M_TOT*D_MODEL];
__device__ __half h_v [M_TOT*D_MODEL];
__device__ __half h_wq[D_MODEL*D_MODEL];
__device__ __half h_wk[D_MODEL*D_MODEL];
__device__ __half h_wv[D_MODEL*D_MODEL];
__device__ __half h_wo[D_MODEL*D_MODEL];
// intermediates (fp16 pairs as uint32)
__device__ uint32_t g_Qh [BATCH*NHEAD*SEQ*(DK/2)];   // [bh][s][32 pairs(d)] pre-scaled by 0.125*log2e
__device__ uint32_t g_Kh [BATCH*NHEAD*SEQ*(DK/2)];   // [bh][s][32 pairs(d)]
__device__ uint32_t g_Vth[BATCH*NHEAD*DK*(SEQ/2)];   // [bh][d][1024 pairs(s)]
__device__ uint32_t g_AOh[M_TOT*(D_MODEL/2)];        // attention out, fp16 pairs
__device__ uint32_t g_Mb [BATCH*SEQ*(SEQ/32)];       // mask bitwords [b][s][64]

// ---------------------------------------------------------------------------
__device__ __forceinline__ uint32_t pk2(float a, float b) {
    __half2 h = __floats2half2_rn(a, b);
    return *(uint32_t*)&h;
}
__device__ __forceinline__ uint32_t smem_u32(const void* p) {
    uint32_t a;
    asm("{ .reg .u64 t; cvta.to.shared.u64 t, %1; cvt.u32.u64 %0, t; }" : "=r"(a) : "l"(p));
    return a;
}
__device__ __forceinline__ void mma_f16(float* d, const uint32_t* a, const uint32_t* b) {
    asm volatile(
        "mma.sync.aligned.m16n8k16.row.col.f32.f16.f16.f32 "
        "{%0,%1,%2,%3}, {%4,%5,%6,%7}, {%8,%9}, {%0,%1,%2,%3};"
        : "+f"(d[0]), "+f"(d[1]), "+f"(d[2]), "+f"(d[3])
        : "r"(a[0]), "r"(a[1]), "r"(a[2]), "r"(a[3]), "r"(b[0]), "r"(b[1]));
}
#define CP16(dst, src) \
    asm volatile("cp.async.cg.shared.global [%0], [%1], 16;" :: "r"(dst), "l"(src))
#define CP_COMMIT() asm volatile("cp.async.commit_group;" ::: "memory")
#define CP_WAIT(n)  asm volatile("cp.async.wait_group %0;" :: "n"(n) : "memory")

// ---------------------------------------------------------------------------
// Pre-pass: fused fp32->fp16 for 3 activations + 4 weights (z dim)
// ---------------------------------------------------------------------------
#define ACT4 (M_TOT * D_MODEL / 4)
#define W4   (D_MODEL * D_MODEL / 4)

__global__ void prepass_half(
    const float4* __restrict__ q,  const float4* __restrict__ k,  const float4* __restrict__ v,
    const float4* __restrict__ wq, const float4* __restrict__ wk,
    const float4* __restrict__ wv, const float4* __restrict__ wo,
    uint2* dq, uint2* dk, uint2* dv, uint2* dwq, uint2* dwk, uint2* dwv, uint2* dwo)
{
    const int z = blockIdx.z;
    const int i = blockIdx.x * blockDim.x + threadIdx.x;
    const float4* s;
    uint2* d;
    int n;
    switch (z) {
        case 0: s = q;  d = dq;  n = ACT4; break;
        case 1: s = k;  d = dk;  n = ACT4; break;
        case 2: s = v;  d = dv;  n = ACT4; break;
        case 3: s = wq; d = dwq; n = W4;   break;
        case 4: s = wk; d = dwk; n = W4;   break;
        case 5: s = wv; d = dwv; n = W4;   break;
        default: s = wo; d = dwo; n = W4;  break;
    }
    if (i < n) {
        float4 x = s[i];
        d[i] = make_uint2(pk2(x.x, x.y), pk2(x.z, x.w));
    }
}
__global__ void mask_bits(const int* __restrict__ mask, uint32_t* __restrict__ bits) {
    int wi   = blockIdx.x * 8 + (threadIdx.x >> 5);
    int lane = threadIdx.x & 31;
    int v = mask[(size_t)wi * 32 + lane];
    uint32_t b = __ballot_sync(0xffffffffu, v != 0);
    if (lane == 0) bits[wi] = b;
}

// ---------------------------------------------------------------------------
// fp16 cp.async GEMM body, single-barrier multistage pipeline.
// C = A[M,1024] @ W[1024,1024]^T + bias
// mode 0: fp32 row-major; mode 1: fp16 pairs head-split, scaled by oscale;
// mode 2: fp16 pairs Vt layout (bias by row m)
// ---------------------------------------------------------------------------
#define GP 20
#define NSTG 4
#define STG_U32 (2 * 128 * GP)
#define GEMM_SMEM (NSTG * STG_U32 * 4)   // 81920 B

__device__ __forceinline__ void gemm_issue(
    const __half* __restrict__ A, const __half* __restrict__ W,
    int m0, int n0, int k0, uint32_t sbase, int st)
{
    const int tid = threadIdx.x;
    const uint32_t abuf = sbase + (st * STG_U32) * 4;
    const uint32_t bbuf = abuf + 128 * GP * 4;
#pragma unroll
    for (int t = 0; t < 2; t++) {
        int c   = tid + t * 256;
        int row = c >> 2;
        int seg = c & 3;
        CP16(abuf + (row * GP + seg * 4) * 4, A + (size_t)(m0 + row) * 1024 + k0 + seg * 8);
        CP16(bbuf + (row * GP + seg * 4) * 4, W + (size_t)(n0 + row) * 1024 + k0 + seg * 8);
    }
}

__device__ __forceinline__ void gemm_body(
    const __half* __restrict__ A, const __half* __restrict__ W,
    const float* __restrict__ bias, void* __restrict__ C,
    int mode, float oscale, int m0, int n0, uint32_t* su)
{
    const uint32_t sbase = smem_u32(su);
    const int tid  = threadIdx.x;
    const int wid  = tid >> 5;
    const int lane = tid & 31;
    const int quad = lane >> 2;
    const int qt   = lane & 3;
    const int wm   = wid >> 2;
    const int wn   = wid & 3;

    float acc[4][4][4];
#pragma unroll
    for (int mf = 0; mf < 4; mf++)
#pragma unroll
        for (int nf = 0; nf < 4; nf++)
#pragma unroll
            for (int j = 0; j < 4; j++) acc[mf][nf][j] = 0.f;

#pragma unroll
    for (int i = 0; i < NSTG - 1; i++) {
        gemm_issue(A, W, m0, n0, i * 32, sbase, i);
        CP_COMMIT();
    }

    for (int s = 0; s < 32; s++) {
        CP_WAIT(NSTG - 2);   // my copies of stage s complete (N-1 pending before wait)
        __syncthreads();     // all warps: stage s visible AND stage s-1 compute done
        if (s + NSTG - 1 < 32)
            gemm_issue(A, W, m0, n0, (s + NSTG - 1) * 32, sbase, (s + NSTG - 1) % NSTG);
        CP_COMMIT();         // unconditional: keeps pending count exact at tail

        const uint32_t* Au = su + (s % NSTG) * STG_U32;
        const uint32_t* Bu = Au + 128 * GP;
#pragma unroll
        for (int kd = 0; kd < 2; kd++) {
            uint32_t af[4][4];
#pragma unroll
            for (int mf = 0; mf < 4; mf++) {
                const uint32_t* ap = Au + (wm * 64 + mf * 16 + quad) * GP + kd * 8 + qt;
                af[mf][0] = ap[0];
                af[mf][1] = ap[8 * GP];
                af[mf][2] = ap[4];
                af[mf][3] = ap[8 * GP + 4];
            }
            uint32_t bf[4][2];
#pragma unroll
            for (int nf = 0; nf < 4; nf++) {
                const uint32_t* bp = Bu + (wn * 32 + nf * 8 + quad) * GP + kd * 8 + qt;
                bf[nf][0] = bp[0];
                bf[nf][1] = bp[4];
            }
#pragma unroll
            for (int mf = 0; mf < 4; mf++)
#pragma unroll
                for (int nf = 0; nf < 4; nf++)
                    mma_f16(acc[mf][nf], af[mf], bf[nf]);
        }
    }

#pragma unroll
    for (int mf = 0; mf < 4; mf++) {
#pragma unroll
        for (int nf = 0; nf < 4; nf++) {
            const int col = n0 + wn * 32 + nf * 8 + qt * 2;
#pragma unroll
            for (int jr = 0; jr < 2; jr++) {
                const int m = m0 + wm * 64 + mf * 16 + quad + 8 * jr;
                float v0 = acc[mf][nf][2 * jr];
                float v1 = acc[mf][nf][2 * jr + 1];
                if (mode == 0) {
                    v0 += bias[col]; v1 += bias[col + 1];
                    *(float2*)((float*)C + (size_t)m * D_MODEL + col) = make_float2(v0, v1);
                } else if (mode == 1) {
                    v0 = (v0 + bias[col]) * oscale;
                    v1 = (v1 + bias[col + 1]) * oscale;
                    const int bb = m >> 11, sq = m & (SEQ - 1);
                    const int h = col >> 6, pairp = (col & 63) >> 1;
                    ((uint32_t*)C)[((size_t)(bb * NHEAD + h) * SEQ + sq) * (DK/2) + pairp] = pk2(v0, v1);
                } else {
                    const float bv = bias[m];
                    v0 += bv; v1 += bv;
                    const int bb = col >> 11, sq = col & (SEQ - 1);
                    const int h = m >> 6, dk = m & (DK - 1);
                    ((uint32_t*)C)[((size_t)(bb * NHEAD + h) * DK + dk) * (SEQ/2) + (sq >> 1)] = pk2(v0, v1);
                }
            }
        }
    }
}

// Q pre-scale: 1/sqrt(64) * log2(e) so softmax runs in the exp2 domain.
#define QSCALE (0.125f * 1.4426950408889634f)

__global__ void __launch_bounds__(256, 2) gemm_qkv(
    uint32_t* outQ, uint32_t* outK, uint32_t* outVt,
    const float* __restrict__ bq, const float* __restrict__ bk, const float* __restrict__ bv)
{
    extern __shared__ uint32_t su[];
    const int z = blockIdx.z;
    if (z == 0)      gemm_body(h_q,  h_wq, bq, outQ,  1, QSCALE, blockIdx.y * 128, blockIdx.x * 128, su);
    else if (z == 1) gemm_body(h_k,  h_wk, bk, outK,  1, 1.0f,   blockIdx.y * 128, blockIdx.x * 128, su);
    else             gemm_body(h_wv, h_v,  bv, outVt, 2, 1.0f,   blockIdx.x * 128, blockIdx.y * 128, su);
}

__global__ void __launch_bounds__(256, 2) gemm_out(
    const float* __restrict__ bias, float* __restrict__ C)
{
    extern __shared__ uint32_t su[];
    gemm_body((const __half*)g_AOh, h_wo, bias, C, 0, 1.0f, blockIdx.y * 128, blockIdx.x * 128, su);
}

// ---------------------------------------------------------------------------
// Flash attention, fp16 mma.m16n8k16. Register-resident P, hoisted Q frags,
// 3-stage cp.async K/V pipeline with ONE barrier per tile, bitmask mask,
// log2-domain softmax (exp2f). CTA: 128 q x one (b,h), 8 warps, 2 CTAs/SM.
// ---------------------------------------------------------------------------
#define QP 36
#define KP 36
#define VP 36
#define ANST 3
#define ATTN_SMEM ((128*QP + ANST*64*KP + ANST*64*VP) * 4)   // 73728 B

__device__ __forceinline__ void attn_issue(
    const uint32_t* __restrict__ Kg, const uint32_t* __restrict__ Vg,
    int kt, uint32_t kbase, uint32_t vbase)
{
    const int tid = threadIdx.x;
#pragma unroll
    for (int t = 0; t < 2; t++) {
        int f   = tid + t * 256;    // 0..511 : 64 rows x 8 segments
        int row = f >> 3;
        int seg = f & 7;
        CP16(kbase + (row * KP + seg * 4) * 4,
             Kg + (size_t)(kt + row) * (DK/2) + seg * 4);
        CP16(vbase + (row * VP + seg * 4) * 4,
             Vg + (size_t)row * (SEQ/2) + (kt >> 1) + seg * 4);
    }
}

__global__ void __launch_bounds__(256, 2) attn_kernel()
{
    extern __shared__ uint32_t su[];
    uint32_t* Qp  = su;                        // [128][QP]
    uint32_t* Kp0 = Qp + 128 * QP;             // [64][KP] x3 stages
    uint32_t* Vp0 = Kp0 + ANST * 64 * KP;      // [64][VP] x3 stages
    const uint32_t kb = smem_u32(Kp0);
    const uint32_t vb = smem_u32(Vp0);

    const int tid  = threadIdx.x;
    const int w    = tid >> 5;
    const int lane = tid & 31;
    const int quad = lane >> 2;
    const int qt   = lane & 3;
    const int bh   = blockIdx.y;
    const int b    = bh >> 4;
    const int h    = bh & 15;
    const int q0   = blockIdx.x * 128;
    const int r0   = w * 16 + quad;

    const uint32_t* Qg = g_Qh  + ((size_t)bh * SEQ + q0) * (DK/2);
    const uint32_t* Kg = g_Kh  + (size_t)bh * SEQ * (DK/2);
    const uint32_t* Vg = g_Vth + (size_t)bh * DK * (SEQ/2);

    // Prologue: issue tiles 0 and 1, then stage Q and hoist fragments.
    attn_issue(Kg, Vg, 0,  kb,                vb);
    CP_COMMIT();
    attn_issue(Kg, Vg, 64, kb + 64 * KP * 4,  vb + 64 * VP * 4);
    CP_COMMIT();

#pragma unroll
    for (int t = 0; t < 8; t++) {
        int f = tid + t * 256, row = f >> 4, c2 = (f & 15) * 2;
        *(uint2*)(Qp + row * QP + c2) = *(const uint2*)(Qg + (size_t)row * (DK/2) + c2);
    }
    __syncthreads();

    uint32_t qa[4][4];
#pragma unroll
    for (int kd = 0; kd < 4; kd++) {
        const uint32_t* ap = Qp + r0 * QP + kd * 8 + qt;
        qa[kd][0] = ap[0];
        qa[kd][1] = ap[8 * QP];
        qa[kd][2] = ap[4];
        qa[kd][3] = ap[8 * QP + 4];
    }

    float oacc[8][4];
#pragma unroll
    for (int nf = 0; nf < 8; nf++)
#pragma unroll
        for (int j = 0; j < 4; j++) oacc[nf][j] = 0.f;
    float mi[2] = {-INFINITY, -INFINITY};
    float li[2] = {0.f, 0.f};

    for (int t = 0; t < 32; t++) {
        const int st = t % ANST;
        const int kt = t * 64;

        CP_WAIT(1);        // my copies of tile t complete (2 groups pending before)
        __syncthreads();   // all warps: tile t visible AND tile t-1 compute done
        if (t + 2 < 32) {
            const int si = (t + 2) % ANST;   // == (t-1)%ANST: freed by the barrier
            attn_issue(Kg, Vg, kt + 128, kb + si * 64 * KP * 4,
                                          vb + si * 64 * VP * 4);
        }
        CP_COMMIT();       // unconditional: pending count stays exact at tail

        const uint32_t* Kc = Kp0 + st * 64 * KP;
        const uint32_t* Vc = Vp0 + st * 64 * VP;

        // ---- QK^T (Q pre-scaled by 0.125*log2e) ----
        float sacc[8][4];
#pragma unroll
        for (int nf = 0; nf < 8; nf++)
#pragma unroll
            for (int j = 0; j < 4; j++) sacc[nf][j] = 0.f;

#pragma unroll
        for (int kd = 0; kd < 4; kd++) {
#pragma unroll
            for (int nf = 0; nf < 8; nf++) {
                uint32_t bfr[2];
                const uint32_t* bp = Kc + (nf * 8 + quad) * KP + kd * 8 + qt;
                bfr[0] = bp[0];
                bfr[1] = bp[4];
                mma_f16(sacc[nf], qa[kd], bfr);
            }
        }

        // ---- bitmask + online softmax (log2 domain) ----
        uint32_t pe[8][2];
#pragma unroll
        for (int r = 0; r < 2; r++) {
            const int qr = q0 + r0 + r * 8;
            uint2 mw = *(const uint2*)(g_Mb + ((size_t)b * SEQ + qr) * (SEQ/32) + (kt >> 5));
            float p[16];
            float mx = -INFINITY;
#pragma unroll
            for (int nf = 0; nf < 8; nf++) {
                const uint32_t wsel = (nf < 4) ? mw.x : mw.y;
                const int bit = (nf * 8 + qt * 2) & 31;
                float s0 = ((wsel >> bit) & 1u)       ? sacc[nf][2 * r]     : -INFINITY;
                float s1 = ((wsel >> (bit + 1)) & 1u) ? sacc[nf][2 * r + 1] : -INFINITY;
                p[2 * nf]     = s0;
                p[2 * nf + 1] = s1;
                mx = fmaxf(mx, fmaxf(s0, s1));
            }
            mx = fmaxf(mx, __shfl_xor_sync(0xffffffffu, mx, 1));
            mx = fmaxf(mx, __shfl_xor_sync(0xffffffffu, mx, 2));
            const float mnew = fmaxf(mi[r], mx);
            const float al   = exp2f(mi[r] - mnew);
            float rs = 0.f;
#pragma unroll
            for (int nf = 0; nf < 8; nf++) {
                float e0 = exp2f(p[2 * nf]     - mnew);
                float e1 = exp2f(p[2 * nf + 1] - mnew);
                rs += e0 + e1;
                pe[nf][r] = pk2(e0, e1);
            }
            rs += __shfl_xor_sync(0xffffffffu, rs, 1);
            rs += __shfl_xor_sync(0xffffffffu, rs, 2);
            li[r] = li[r] * al + rs;
            mi[r] = mnew;
#pragma unroll
            for (int nf = 0; nf < 8; nf++) {
                oacc[nf][2 * r]     *= al;
                oacc[nf][2 * r + 1] *= al;
            }
        }

        // ---- PV: O += P @ V, P A-frags direct from registers ----
#pragma unroll
        for (int kk = 0; kk < 4; kk++) {
            uint32_t a[4];
            a[0] = pe[2 * kk][0];
            a[1] = pe[2 * kk][1];
            a[2] = pe[2 * kk + 1][0];
            a[3] = pe[2 * kk + 1][1];
#pragma unroll
            for (int nf = 0; nf < 8; nf++) {
                uint32_t bfr[2];
                const uint32_t* bp = Vc + (nf * 8 + quad) * VP + kk * 8 + qt;
                bfr[0] = bp[0];
                bfr[1] = bp[4];
                mma_f16(oacc[nf], a, bfr);
            }
        }
    }

    // Epilogue: fp16 pairs into g_AOh
#pragma unroll
    for (int r = 0; r < 2; r++) {
        const int qr = q0 + r0 + 8 * r;
        const float inv = 1.f / li[r];
        uint32_t* dst = g_AOh + (size_t)(b * SEQ + qr) * (D_MODEL/2) + h * (DK/2);
#pragma unroll
        for (int nf = 0; nf < 8; nf++)
            dst[nf * 4 + qt] = pk2(oacc[nf][2 * r] * inv, oacc[nf][2 * r + 1] * inv);
    }
}

// ---------------------------------------------------------------------------
extern "C" void kernel_launch(void* const* d_in, const int* in_sizes, int n_in,
                              void* d_out, int out_size)
{
    const float* q   = (const float*)d_in[0];
    const float* k   = (const float*)d_in[1];
    const float* v   = (const float*)d_in[2];
    const int*   msk = (const int*)  d_in[3];
    const float* b_q = (const float*)d_in[5];
    const float* b_k = (const float*)d_in[7];
    const float* b_v = (const float*)d_in[9];
    const float* b_o = (const float*)d_in[11];
    float* out = (float*)d_out;

    void *hq, *hk, *hv, *hwq, *hwk, *hwv, *hwo, *gQ, *gK, *gVt, *gMb;
    cudaGetSymbolAddress(&hq,  h_q);
    cudaGetSymbolAddress(&hk,  h_k);
    cudaGetSymbolAddress(&hv,  h_v);
    cudaGetSymbolAddress(&hwq, h_wq);
    cudaGetSymbolAddress(&hwk, h_wk);
    cudaGetSymbolAddress(&hwv, h_wv);
    cudaGetSymbolAddress(&hwo, h_wo);
    cudaGetSymbolAddress(&gQ,  g_Qh);
    cudaGetSymbolAddress(&gK,  g_Kh);
    cudaGetSymbolAddress(&gVt, g_Vth);
    cudaGetSymbolAddress(&gMb, g_Mb);

    cudaFuncSetAttribute(gemm_qkv,    cudaFuncAttributeMaxDynamicSharedMemorySize, GEMM_SMEM);
    cudaFuncSetAttribute(gemm_out,    cudaFuncAttributeMaxDynamicSharedMemorySize, GEMM_SMEM);
    cudaFuncSetAttribute(attn_kernel, cudaFuncAttributeMaxDynamicSharedMemorySize, ATTN_SMEM);

    // Fused fp16 pre-pass (acts + weights) + mask bitwords
    dim3 pgrid(ACT4 / 256, 1, 7);
    prepass_half<<<pgrid, 256>>>(
        (const float4*)q, (const float4*)k, (const float4*)v,
        (const float4*)d_in[4], (const float4*)d_in[6],
        (const float4*)d_in[8], (const float4*)d_in[10],
        (uint2*)hq, (uint2*)hk, (uint2*)hv,
        (uint2*)hwq, (uint2*)hwk, (uint2*)hwv, (uint2*)hwo);
    mask_bits<<<BATCH * SEQ * (SEQ/32) / 8, 256>>>(msk, (uint32_t*)gMb);

    dim3 qkvgrid(8, 32, 3);
    gemm_qkv<<<qkvgrid, 256, GEMM_SMEM>>>((uint32_t*)gQ, (uint32_t*)gK, (uint32_t*)gVt,
                                          b_q, b_k, b_v);

    dim3 agrid(SEQ / 128, BATCH * NHEAD);
    attn_kernel<<<agrid, 256, ATTN_SMEM>>>();

    dim3 ogrid(8, 32);
    gemm_out<<<ogrid, 256, GEMM_SMEM>>>(b_o, out);
}

// round 16
// speedup vs baseline: 10.3650x; 1.0275x over previous
#include <cuda_runtime.h>
#include <cuda_fp16.h>
#include <math.h>
#include <stdint.h>

#define D_MODEL 1024
#define NHEAD   16
#define DK      64
#define BATCH   2
#define SEQ     2048
#define M_TOT   (BATCH*SEQ)   // 4096

// fp16 copies of inputs (pre-pass)
__device__ __half h_q [M_TOT*D_MODEL];
__device__ __half h_k [M_TOT*D_MODEL];
__device__ __half h_v [M_TOT*D_MODEL];
__device__ __half h_wq[D_MODEL*D_MODEL];
__device__ __half h_wk[D_MODEL*D_MODEL];
__device__ __half h_wv[D_MODEL*D_MODEL];
__device__ __half h_wo[D_MODEL*D_MODEL];
// intermediates (fp16 pairs as uint32)
__device__ uint32_t g_Qh [BATCH*NHEAD*SEQ*(DK/2)];   // [bh][s][32 pairs(d)] pre-scaled by 0.125*log2e
__device__ uint32_t g_Kh [BATCH*NHEAD*SEQ*(DK/2)];   // [bh][s][32 pairs(d)]
__device__ uint32_t g_Vth[BATCH*NHEAD*DK*(SEQ/2)];   // [bh][d][1024 pairs(s)]
__device__ uint32_t g_AOh[M_TOT*(D_MODEL/2)];        // attention out, fp16 pairs
__device__ uint32_t g_Mb [BATCH*SEQ*(SEQ/32)];       // mask bitwords [b][s][64]

// ---------------------------------------------------------------------------
__device__ __forceinline__ uint32_t pk2(float a, float b) {
    __half2 h = __floats2half2_rn(a, b);
    return *(uint32_t*)&h;
}
__device__ __forceinline__ uint32_t smem_u32(const void* p) {
    uint32_t a;
    asm("{ .reg .u64 t; cvta.to.shared.u64 t, %1; cvt.u32.u64 %0, t; }" : "=r"(a) : "l"(p));
    return a;
}
__device__ __forceinline__ void mma_f16(float* d, const uint32_t* a, const uint32_t* b) {
    asm volatile(
        "mma.sync.aligned.m16n8k16.row.col.f32.f16.f16.f32 "
        "{%0,%1,%2,%3}, {%4,%5,%6,%7}, {%8,%9}, {%0,%1,%2,%3};"
        : "+f"(d[0]), "+f"(d[1]), "+f"(d[2]), "+f"(d[3])
        : "r"(a[0]), "r"(a[1]), "r"(a[2]), "r"(a[3]), "r"(b[0]), "r"(b[1]));
}
#define LDSM4(r0, r1, r2, r3, addr) \
    asm volatile("ldmatrix.sync.aligned.m8n8.x4.shared.b16 {%0,%1,%2,%3}, [%4];" \
                 : "=r"(r0), "=r"(r1), "=r"(r2), "=r"(r3) : "r"(addr))
#define CP16(dst, src) \
    asm volatile("cp.async.cg.shared.global [%0], [%1], 16;" :: "r"(dst), "l"(src))
#define CP_COMMIT() asm volatile("cp.async.commit_group;" ::: "memory")
#define CP_WAIT(n)  asm volatile("cp.async.wait_group %0;" :: "n"(n) : "memory")

// ---------------------------------------------------------------------------
// Pre-pass: fused fp32->fp16 for 3 activations + 4 weights (z dim)
// ---------------------------------------------------------------------------
#define ACT4 (M_TOT * D_MODEL / 4)
#define W4   (D_MODEL * D_MODEL / 4)

__global__ void prepass_half(
    const float4* __restrict__ q,  const float4* __restrict__ k,  const float4* __restrict__ v,
    const float4* __restrict__ wq, const float4* __restrict__ wk,
    const float4* __restrict__ wv, const float4* __restrict__ wo,
    uint2* dq, uint2* dk, uint2* dv, uint2* dwq, uint2* dwk, uint2* dwv, uint2* dwo)
{
    const int z = blockIdx.z;
    const int i = blockIdx.x * blockDim.x + threadIdx.x;
    const float4* s;
    uint2* d;
    int n;
    switch (z) {
        case 0: s = q;  d = dq;  n = ACT4; break;
        case 1: s = k;  d = dk;  n = ACT4; break;
        case 2: s = v;  d = dv;  n = ACT4; break;
        case 3: s = wq; d = dwq; n = W4;   break;
        case 4: s = wk; d = dwk; n = W4;   break;
        case 5: s = wv; d = dwv; n = W4;   break;
        default: s = wo; d = dwo; n = W4;  break;
    }
    if (i < n) {
        float4 x = s[i];
        d[i] = make_uint2(pk2(x.x, x.y), pk2(x.z, x.w));
    }
}
__global__ void mask_bits(const int* __restrict__ mask, uint32_t* __restrict__ bits) {
    int wi   = blockIdx.x * 8 + (threadIdx.x >> 5);
    int lane = threadIdx.x & 31;
    int v = mask[(size_t)wi * 32 + lane];
    uint32_t b = __ballot_sync(0xffffffffu, v != 0);
    if (lane == 0) bits[wi] = b;
}

// ---------------------------------------------------------------------------
// fp16 cp.async GEMM body, single-barrier multistage pipeline (proven R14).
// ---------------------------------------------------------------------------
#define GP 20
#define NSTG 4
#define STG_U32 (2 * 128 * GP)
#define GEMM_SMEM (NSTG * STG_U32 * 4)   // 81920 B

__device__ __forceinline__ void gemm_issue(
    const __half* __restrict__ A, const __half* __restrict__ W,
    int m0, int n0, int k0, uint32_t sbase, int st)
{
    const int tid = threadIdx.x;
    const uint32_t abuf = sbase + (st * STG_U32) * 4;
    const uint32_t bbuf = abuf + 128 * GP * 4;
#pragma unroll
    for (int t = 0; t < 2; t++) {
        int c   = tid + t * 256;
        int row = c >> 2;
        int seg = c & 3;
        CP16(abuf + (row * GP + seg * 4) * 4, A + (size_t)(m0 + row) * 1024 + k0 + seg * 8);
        CP16(bbuf + (row * GP + seg * 4) * 4, W + (size_t)(n0 + row) * 1024 + k0 + seg * 8);
    }
}

__device__ __forceinline__ void gemm_body(
    const __half* __restrict__ A, const __half* __restrict__ W,
    const float* __restrict__ bias, void* __restrict__ C,
    int mode, float oscale, int m0, int n0, uint32_t* su)
{
    const uint32_t sbase = smem_u32(su);
    const int tid  = threadIdx.x;
    const int wid  = tid >> 5;
    const int lane = tid & 31;
    const int quad = lane >> 2;
    const int qt   = lane & 3;
    const int wm   = wid >> 2;
    const int wn   = wid & 3;

    float acc[4][4][4];
#pragma unroll
    for (int mf = 0; mf < 4; mf++)
#pragma unroll
        for (int nf = 0; nf < 4; nf++)
#pragma unroll
            for (int j = 0; j < 4; j++) acc[mf][nf][j] = 0.f;

#pragma unroll
    for (int i = 0; i < NSTG - 1; i++) {
        gemm_issue(A, W, m0, n0, i * 32, sbase, i);
        CP_COMMIT();
    }

    for (int s = 0; s < 32; s++) {
        CP_WAIT(NSTG - 2);
        __syncthreads();
        if (s + NSTG - 1 < 32)
            gemm_issue(A, W, m0, n0, (s + NSTG - 1) * 32, sbase, (s + NSTG - 1) % NSTG);
        CP_COMMIT();

        const uint32_t* Au = su + (s % NSTG) * STG_U32;
        const uint32_t* Bu = Au + 128 * GP;
#pragma unroll
        for (int kd = 0; kd < 2; kd++) {
            uint32_t af[4][4];
#pragma unroll
            for (int mf = 0; mf < 4; mf++) {
                const uint32_t* ap = Au + (wm * 64 + mf * 16 + quad) * GP + kd * 8 + qt;
                af[mf][0] = ap[0];
                af[mf][1] = ap[8 * GP];
                af[mf][2] = ap[4];
                af[mf][3] = ap[8 * GP + 4];
            }
            uint32_t bf[4][2];
#pragma unroll
            for (int nf = 0; nf < 4; nf++) {
                const uint32_t* bp = Bu + (wn * 32 + nf * 8 + quad) * GP + kd * 8 + qt;
                bf[nf][0] = bp[0];
                bf[nf][1] = bp[4];
            }
#pragma unroll
            for (int mf = 0; mf < 4; mf++)
#pragma unroll
                for (int nf = 0; nf < 4; nf++)
                    mma_f16(acc[mf][nf], af[mf], bf[nf]);
        }
    }

#pragma unroll
    for (int mf = 0; mf < 4; mf++) {
#pragma unroll
        for (int nf = 0; nf < 4; nf++) {
            const int col = n0 + wn * 32 + nf * 8 + qt * 2;
#pragma unroll
            for (int jr = 0; jr < 2; jr++) {
                const int m = m0 + wm * 64 + mf * 16 + quad + 8 * jr;
                float v0 = acc[mf][nf][2 * jr];
                float v1 = acc[mf][nf][2 * jr + 1];
                if (mode == 0) {
                    v0 += bias[col]; v1 += bias[col + 1];
                    *(float2*)((float*)C + (size_t)m * D_MODEL + col) = make_float2(v0, v1);
                } else if (mode == 1) {
                    v0 = (v0 + bias[col]) * oscale;
                    v1 = (v1 + bias[col + 1]) * oscale;
                    const int bb = m >> 11, sq = m & (SEQ - 1);
                    const int h = col >> 6, pairp = (col & 63) >> 1;
                    ((uint32_t*)C)[((size_t)(bb * NHEAD + h) * SEQ + sq) * (DK/2) + pairp] = pk2(v0, v1);
                } else {
                    const float bv = bias[m];
                    v0 += bv; v1 += bv;
                    const int bb = col >> 11, sq = col & (SEQ - 1);
                    const int h = m >> 6, dk = m & (DK - 1);
                    ((uint32_t*)C)[((size_t)(bb * NHEAD + h) * DK + dk) * (SEQ/2) + (sq >> 1)] = pk2(v0, v1);
                }
            }
        }
    }
}

#define QSCALE (0.125f * 1.4426950408889634f)

__global__ void __launch_bounds__(256, 2) gemm_qkv(
    uint32_t* outQ, uint32_t* outK, uint32_t* outVt,
    const float* __restrict__ bq, const float* __restrict__ bk, const float* __restrict__ bv)
{
    extern __shared__ uint32_t su[];
    const int z = blockIdx.z;
    if (z == 0)      gemm_body(h_q,  h_wq, bq, outQ,  1, QSCALE, blockIdx.y * 128, blockIdx.x * 128, su);
    else if (z == 1) gemm_body(h_k,  h_wk, bk, outK,  1, 1.0f,   blockIdx.y * 128, blockIdx.x * 128, su);
    else             gemm_body(h_wv, h_v,  bv, outVt, 2, 1.0f,   blockIdx.x * 128, blockIdx.y * 128, su);
}

__global__ void __launch_bounds__(256, 2) gemm_out(
    const float* __restrict__ bias, float* __restrict__ C)
{
    extern __shared__ uint32_t su[];
    gemm_body((const __half*)g_AOh, h_wo, bias, C, 0, 1.0f, blockIdx.y * 128, blockIdx.x * 128, su);
}

// ---------------------------------------------------------------------------
// Flash attention: fp16 mma, register P, ldmatrix.x4 B-fragments, mask
// fast-path, skip-rescale, 3-stage cp.async, exp2-domain softmax.
// ---------------------------------------------------------------------------
#define QP 36
#define KP 36
#define VP 36
#define ANST 3
#define ATTN_SMEM ((128*QP + ANST*64*KP + ANST*64*VP) * 4)   // 73728 B

__device__ __forceinline__ void attn_issue(
    const uint32_t* __restrict__ Kg, const uint32_t* __restrict__ Vg,
    int kt, uint32_t kbase, uint32_t vbase)
{
    const int tid = threadIdx.x;
#pragma unroll
    for (int t = 0; t < 2; t++) {
        int f   = tid + t * 256;
        int row = f >> 3;
        int seg = f & 7;
        CP16(kbase + (row * KP + seg * 4) * 4,
             Kg + (size_t)(kt + row) * (DK/2) + seg * 4);
        CP16(vbase + (row * VP + seg * 4) * 4,
             Vg + (size_t)row * (SEQ/2) + (kt >> 1) + seg * 4);
    }
}

__global__ void __launch_bounds__(256, 2) attn_kernel()
{
    extern __shared__ uint32_t su[];
    uint32_t* Qp  = su;                        // [128][QP]
    uint32_t* Kp0 = Qp + 128 * QP;             // [64][KP] x3 stages
    uint32_t* Vp0 = Kp0 + ANST * 64 * KP;      // [64][VP] x3 stages
    const uint32_t kb = smem_u32(Kp0);
    const uint32_t vb = smem_u32(Vp0);

    const int tid  = threadIdx.x;
    const int w    = tid >> 5;
    const int lane = tid & 31;
    const int quad = lane >> 2;
    const int qt   = lane & 3;
    const int bh   = blockIdx.y;
    const int b    = bh >> 4;
    const int h    = bh & 15;
    const int q0   = blockIdx.x * 128;
    const int r0   = w * 16 + quad;

    // ldmatrix per-lane row offset (u32 units), shared by K and V (KP==VP):
    // matrix j = lane>>3 covers (nf-sub j>>1, d/key half j&1); row r = lane&7.
    const int lmj = lane >> 3, lmr = lane & 7;
    const uint32_t lm_off = (uint32_t)(((lmj >> 1) * 8 + lmr) * KP + (lmj & 1) * 4) * 4;

    const uint32_t* Qg = g_Qh  + ((size_t)bh * SEQ + q0) * (DK/2);
    const uint32_t* Kg = g_Kh  + (size_t)bh * SEQ * (DK/2);
    const uint32_t* Vg = g_Vth + (size_t)bh * DK * (SEQ/2);

    attn_issue(Kg, Vg, 0,  kb,                vb);
    CP_COMMIT();
    attn_issue(Kg, Vg, 64, kb + 64 * KP * 4,  vb + 64 * VP * 4);
    CP_COMMIT();

#pragma unroll
    for (int t = 0; t < 8; t++) {
        int f = tid + t * 256, row = f >> 4, c2 = (f & 15) * 2;
        *(uint2*)(Qp + row * QP + c2) = *(const uint2*)(Qg + (size_t)row * (DK/2) + c2);
    }
    __syncthreads();

    uint32_t qa[4][4];
#pragma unroll
    for (int kd = 0; kd < 4; kd++) {
        const uint32_t* ap = Qp + r0 * QP + kd * 8 + qt;
        qa[kd][0] = ap[0];
        qa[kd][1] = ap[8 * QP];
        qa[kd][2] = ap[4];
        qa[kd][3] = ap[8 * QP + 4];
    }

    float oacc[8][4];
#pragma unroll
    for (int nf = 0; nf < 8; nf++)
#pragma unroll
        for (int j = 0; j < 4; j++) oacc[nf][j] = 0.f;
    float mi[2] = {-INFINITY, -INFINITY};
    float li[2] = {0.f, 0.f};

    for (int t = 0; t < 32; t++) {
        const int st = t % ANST;
        const int kt = t * 64;

        CP_WAIT(1);
        __syncthreads();
        if (t + 2 < 32) {
            const int si = (t + 2) % ANST;
            attn_issue(Kg, Vg, kt + 128, kb + si * 64 * KP * 4,
                                          vb + si * 64 * VP * 4);
        }
        CP_COMMIT();

        const uint32_t kaddr = kb + st * 64 * KP * 4 + lm_off;
        const uint32_t vaddr = vb + st * 64 * VP * 4 + lm_off;

        // ---- QK^T via ldmatrix.x4 (2 nf per load) ----
        float sacc[8][4];
#pragma unroll
        for (int nf = 0; nf < 8; nf++)
#pragma unroll
            for (int j = 0; j < 4; j++) sacc[nf][j] = 0.f;

#pragma unroll
        for (int kd = 0; kd < 4; kd++) {
#pragma unroll
            for (int p = 0; p < 4; p++) {
                uint32_t b0, b1, b2, b3;
                LDSM4(b0, b1, b2, b3, kaddr + (uint32_t)(p * 16 * KP + kd * 8) * 4);
                uint32_t f0[2] = {b0, b1};
                uint32_t f1[2] = {b2, b3};
                mma_f16(sacc[2 * p],     qa[kd], f0);
                mma_f16(sacc[2 * p + 1], qa[kd], f1);
            }
        }

        // ---- bitmask (fast-path) + online softmax (exp2 domain) ----
        uint32_t pe[8][2];
#pragma unroll
        for (int r = 0; r < 2; r++) {
            const int qr = q0 + r0 + r * 8;
            uint2 mw = *(const uint2*)(g_Mb + ((size_t)b * SEQ + qr) * (SEQ/32) + (kt >> 5));
            float p[16];
            float mx = -INFINITY;
            if ((mw.x & mw.y) == 0xFFFFFFFFu) {
#pragma unroll
                for (int nf = 0; nf < 8; nf++) {
                    float s0 = sacc[nf][2 * r];
                    float s1 = sacc[nf][2 * r + 1];
                    p[2 * nf]     = s0;
                    p[2 * nf + 1] = s1;
                    mx = fmaxf(mx, fmaxf(s0, s1));
                }
            } else {
#pragma unroll
                for (int nf = 0; nf < 8; nf++) {
                    const uint32_t wsel = (nf < 4) ? mw.x : mw.y;
                    const int bit = (nf * 8 + qt * 2) & 31;
                    float s0 = ((wsel >> bit) & 1u)       ? sacc[nf][2 * r]     : -INFINITY;
                    float s1 = ((wsel >> (bit + 1)) & 1u) ? sacc[nf][2 * r + 1] : -INFINITY;
                    p[2 * nf]     = s0;
                    p[2 * nf + 1] = s1;
                    mx = fmaxf(mx, fmaxf(s0, s1));
                }
            }
            mx = fmaxf(mx, __shfl_xor_sync(0xffffffffu, mx, 1));
            mx = fmaxf(mx, __shfl_xor_sync(0xffffffffu, mx, 2));
            const float mnew = fmaxf(mi[r], mx);
            const bool  chg  = (mnew != mi[r]);
            const float al   = chg ? exp2f(mi[r] - mnew) : 1.0f;
            float rs = 0.f;
#pragma unroll
            for (int nf = 0; nf < 8; nf++) {
                float e0 = exp2f(p[2 * nf]     - mnew);
                float e1 = exp2f(p[2 * nf + 1] - mnew);
                rs += e0 + e1;
                pe[nf][r] = pk2(e0, e1);
            }
            rs += __shfl_xor_sync(0xffffffffu, rs, 1);
            rs += __shfl_xor_sync(0xffffffffu, rs, 2);
            li[r] = li[r] * al + rs;
            mi[r] = mnew;
            if (chg) {
#pragma unroll
                for (int nf = 0; nf < 8; nf++) {
                    oacc[nf][2 * r]     *= al;
                    oacc[nf][2 * r + 1] *= al;
                }
            }
        }

        // ---- PV via ldmatrix.x4 ----
#pragma unroll
        for (int kk = 0; kk < 4; kk++) {
            uint32_t a[4];
            a[0] = pe[2 * kk][0];
            a[1] = pe[2 * kk][1];
            a[2] = pe[2 * kk + 1][0];
            a[3] = pe[2 * kk + 1][1];
#pragma unroll
            for (int p = 0; p < 4; p++) {
                uint32_t b0, b1, b2, b3;
                LDSM4(b0, b1, b2, b3, vaddr + (uint32_t)(p * 16 * VP + kk * 8) * 4);
                uint32_t f0[2] = {b0, b1};
                uint32_t f1[2] = {b2, b3};
                mma_f16(oacc[2 * p],     a, f0);
                mma_f16(oacc[2 * p + 1], a, f1);
            }
        }
    }

    // Epilogue
#pragma unroll
    for (int r = 0; r < 2; r++) {
        const int qr = q0 + r0 + 8 * r;
        const float inv = 1.f / li[r];
        uint32_t* dst = g_AOh + (size_t)(b * SEQ + qr) * (D_MODEL/2) + h * (DK/2);
#pragma unroll
        for (int nf = 0; nf < 8; nf++)
            dst[nf * 4 + qt] = pk2(oacc[nf][2 * r] * inv, oacc[nf][2 * r + 1] * inv);
    }
}

// ---------------------------------------------------------------------------
extern "C" void kernel_launch(void* const* d_in, const int* in_sizes, int n_in,
                              void* d_out, int out_size)
{
    const float* q   = (const float*)d_in[0];
    const float* k   = (const float*)d_in[1];
    const float* v   = (const float*)d_in[2];
    const int*   msk = (const int*)  d_in[3];
    const float* b_q = (const float*)d_in[5];
    const float* b_k = (const float*)d_in[7];
    const float* b_v = (const float*)d_in[9];
    const float* b_o = (const float*)d_in[11];
    float* out = (float*)d_out;

    void *hq, *hk, *hv, *hwq, *hwk, *hwv, *hwo, *gQ, *gK, *gVt, *gMb;
    cudaGetSymbolAddress(&hq,  h_q);
    cudaGetSymbolAddress(&hk,  h_k);
    cudaGetSymbolAddress(&hv,  h_v);
    cudaGetSymbolAddress(&hwq, h_wq);
    cudaGetSymbolAddress(&hwk, h_wk);
    cudaGetSymbolAddress(&hwv, h_wv);
    cudaGetSymbolAddress(&hwo, h_wo);
    cudaGetSymbolAddress(&gQ,  g_Qh);
    cudaGetSymbolAddress(&gK,  g_Kh);
    cudaGetSymbolAddress(&gVt, g_Vth);
    cudaGetSymbolAddress(&gMb, g_Mb);

    cudaFuncSetAttribute(gemm_qkv,    cudaFuncAttributeMaxDynamicSharedMemorySize, GEMM_SMEM);
    cudaFuncSetAttribute(gemm_out,    cudaFuncAttributeMaxDynamicSharedMemorySize, GEMM_SMEM);
    cudaFuncSetAttribute(attn_kernel, cudaFuncAttributeMaxDynamicSharedMemorySize, ATTN_SMEM);

    dim3 pgrid(ACT4 / 256, 1, 7);
    prepass_half<<<pgrid, 256>>>(
        (const float4*)q, (const float4*)k, (const float4*)v,
        (const float4*)d_in[4], (const float4*)d_in[6],
        (const float4*)d_in[8], (const float4*)d_in[10],
        (uint2*)hq, (uint2*)hk, (uint2*)hv,
        (uint2*)hwq, (uint2*)hwk, (uint2*)hwv, (uint2*)hwo);
    mask_bits<<<BATCH * SEQ * (SEQ/32) / 8, 256>>>(msk, (uint32_t*)gMb);

    dim3 qkvgrid(8, 32, 3);
    gemm_qkv<<<qkvgrid, 256, GEMM_SMEM>>>((uint32_t*)gQ, (uint32_t*)gK, (uint32_t*)gVt,
                                          b_q, b_k, b_v);

    dim3 agrid(SEQ / 128, BATCH * NHEAD);
    attn_kernel<<<agrid, 256, ATTN_SMEM>>>();

    dim3 ogrid(8, 32);
    gemm_out<<<ogrid, 256, GEMM_SMEM>>>(b_o, out);
}

// round 17
// speedup vs baseline: 11.2155x; 1.0821x over previous
#include <cuda_runtime.h>
#include <cuda_fp16.h>
#include <math.h>
#include <stdint.h>

#define D_MODEL 1024
#define NHEAD   16
#define DK      64
#define BATCH   2
#define SEQ     2048
#define M_TOT   (BATCH*SEQ)   // 4096

// fp16 copies of inputs (pre-pass)
__device__ __half h_q [M_TOT*D_MODEL];
__device__ __half h_k [M_TOT*D_MODEL];
__device__ __half h_v [M_TOT*D_MODEL];
__device__ __half h_wq[D_MODEL*D_MODEL];
__device__ __half h_wk[D_MODEL*D_MODEL];
__device__ __half h_wv[D_MODEL*D_MODEL];
__device__ __half h_wo[D_MODEL*D_MODEL];
// intermediates (fp16 pairs as uint32)
__device__ uint32_t g_Qh [BATCH*NHEAD*SEQ*(DK/2)];   // [bh][s][32 pairs(d)] pre-scaled by 0.125*log2e
__device__ uint32_t g_Kh [BATCH*NHEAD*SEQ*(DK/2)];   // [bh][s][32 pairs(d)]
__device__ uint32_t g_Vth[BATCH*NHEAD*DK*(SEQ/2)];   // [bh][d][1024 pairs(s)]
__device__ uint32_t g_AOh[M_TOT*(D_MODEL/2)];        // attention out, fp16 pairs
__device__ uint32_t g_Mb [BATCH*SEQ*(SEQ/32)];       // mask bitwords [b][s][64]

// ---------------------------------------------------------------------------
__device__ __forceinline__ uint32_t pk2(float a, float b) {
    __half2 h = __floats2half2_rn(a, b);
    return *(uint32_t*)&h;
}
__device__ __forceinline__ uint32_t smem_u32(const void* p) {
    uint32_t a;
    asm("{ .reg .u64 t; cvta.to.shared.u64 t, %1; cvt.u32.u64 %0, t; }" : "=r"(a) : "l"(p));
    return a;
}
__device__ __forceinline__ void mma_f16(float* d, const uint32_t* a, const uint32_t* b) {
    asm volatile(
        "mma.sync.aligned.m16n8k16.row.col.f32.f16.f16.f32 "
        "{%0,%1,%2,%3}, {%4,%5,%6,%7}, {%8,%9}, {%0,%1,%2,%3};"
        : "+f"(d[0]), "+f"(d[1]), "+f"(d[2]), "+f"(d[3])
        : "r"(a[0]), "r"(a[1]), "r"(a[2]), "r"(a[3]), "r"(b[0]), "r"(b[1]));
}
#define LDSM4(r0, r1, r2, r3, addr) \
    asm volatile("ldmatrix.sync.aligned.m8n8.x4.shared.b16 {%0,%1,%2,%3}, [%4];" \
                 : "=r"(r0), "=r"(r1), "=r"(r2), "=r"(r3) : "r"(addr))
#define CP16(dst, src) \
    asm volatile("cp.async.cg.shared.global [%0], [%1], 16;" :: "r"(dst), "l"(src))
#define CP_COMMIT() asm volatile("cp.async.commit_group;" ::: "memory")
#define CP_WAIT(n)  asm volatile("cp.async.wait_group %0;" :: "n"(n) : "memory")

// ---------------------------------------------------------------------------
// Pre-pass: fused fp32->fp16 for 3 activations + 4 weights (z dim)
// ---------------------------------------------------------------------------
#define ACT4 (M_TOT * D_MODEL / 4)
#define W4   (D_MODEL * D_MODEL / 4)

__global__ void prepass_half(
    const float4* __restrict__ q,  const float4* __restrict__ k,  const float4* __restrict__ v,
    const float4* __restrict__ wq, const float4* __restrict__ wk,
    const float4* __restrict__ wv, const float4* __restrict__ wo,
    uint2* dq, uint2* dk, uint2* dv, uint2* dwq, uint2* dwk, uint2* dwv, uint2* dwo)
{
    const int z = blockIdx.z;
    const int i = blockIdx.x * blockDim.x + threadIdx.x;
    const float4* s;
    uint2* d;
    int n;
    switch (z) {
        case 0: s = q;  d = dq;  n = ACT4; break;
        case 1: s = k;  d = dk;  n = ACT4; break;
        case 2: s = v;  d = dv;  n = ACT4; break;
        case 3: s = wq; d = dwq; n = W4;   break;
        case 4: s = wk; d = dwk; n = W4;   break;
        case 5: s = wv; d = dwv; n = W4;   break;
        default: s = wo; d = dwo; n = W4;  break;
    }
    if (i < n) {
        float4 x = s[i];
        d[i] = make_uint2(pk2(x.x, x.y), pk2(x.z, x.w));
    }
}
__global__ void mask_bits(const int* __restrict__ mask, uint32_t* __restrict__ bits) {
    int wi   = blockIdx.x * 8 + (threadIdx.x >> 5);
    int lane = threadIdx.x & 31;
    int v = mask[(size_t)wi * 32 + lane];
    uint32_t b = __ballot_sync(0xffffffffu, v != 0);
    if (lane == 0) bits[wi] = b;
}

// ---------------------------------------------------------------------------
// fp16 cp.async GEMM body, single-barrier 5-stage pipeline, ldmatrix frags.
// C = A[M,1024] @ W[1024,1024]^T + bias
// ---------------------------------------------------------------------------
#define GP 20
#define NSTG 5
#define STG_U32 (2 * 128 * GP)
#define GEMM_SMEM (NSTG * STG_U32 * 4)   // 102400 B

__device__ __forceinline__ void gemm_issue(
    const __half* __restrict__ A, const __half* __restrict__ W,
    int m0, int n0, int k0, uint32_t sbase, int st)
{
    const int tid = threadIdx.x;
    const uint32_t abuf = sbase + (st * STG_U32) * 4;
    const uint32_t bbuf = abuf + 128 * GP * 4;
#pragma unroll
    for (int t = 0; t < 2; t++) {
        int c   = tid + t * 256;
        int row = c >> 2;
        int seg = c & 3;
        CP16(abuf + (row * GP + seg * 4) * 4, A + (size_t)(m0 + row) * 1024 + k0 + seg * 8);
        CP16(bbuf + (row * GP + seg * 4) * 4, W + (size_t)(n0 + row) * 1024 + k0 + seg * 8);
    }
}

__device__ __forceinline__ void gemm_body(
    const __half* __restrict__ A, const __half* __restrict__ W,
    const float* __restrict__ bias, void* __restrict__ C,
    int mode, float oscale, int m0, int n0, uint32_t* su)
{
    const uint32_t sbase = smem_u32(su);
    const int tid  = threadIdx.x;
    const int wid  = tid >> 5;
    const int lane = tid & 31;
    const int quad = lane >> 2;
    const int qt   = lane & 3;
    const int wm   = wid >> 2;
    const int wn   = wid & 3;

    // ldmatrix per-lane offsets (bytes). j = lane>>3, r = lane&7.
    // A (m16k16): r0=(m,k0) r1=(m+8,k0) r2=(m,k+8h) r3=(m+8,k+8h)
    const int lmr = lane & 7;
    const uint32_t lmA = (uint32_t)(((((lane >> 3) & 1) * 8 + lmr) * GP + (lane >> 4) * 4) * 4);
    // B (two n8k16 frags): r0=(n0,k0) r1=(n0,k+8h) r2=(n0+8,k0) r3=(n0+8,k+8h)
    const uint32_t lmB = (uint32_t)((((lane >> 4) * 8 + lmr) * GP + ((lane >> 3) & 1) * 4) * 4);

    float acc[4][4][4];
#pragma unroll
    for (int mf = 0; mf < 4; mf++)
#pragma unroll
        for (int nf = 0; nf < 4; nf++)
#pragma unroll
            for (int j = 0; j < 4; j++) acc[mf][nf][j] = 0.f;

#pragma unroll
    for (int i = 0; i < NSTG - 1; i++) {
        gemm_issue(A, W, m0, n0, i * 32, sbase, i);
        CP_COMMIT();
    }

    for (int s = 0; s < 32; s++) {
        CP_WAIT(NSTG - 2);
        __syncthreads();
        if (s + NSTG - 1 < 32)
            gemm_issue(A, W, m0, n0, (s + NSTG - 1) * 32, sbase, (s + NSTG - 1) % NSTG);
        CP_COMMIT();

        const uint32_t Ab = sbase + ((s % NSTG) * STG_U32) * 4;
        const uint32_t Bb = Ab + 128 * GP * 4;
#pragma unroll
        for (int kd = 0; kd < 2; kd++) {
            uint32_t af[4][4];
#pragma unroll
            for (int mf = 0; mf < 4; mf++)
                LDSM4(af[mf][0], af[mf][1], af[mf][2], af[mf][3],
                      Ab + (uint32_t)(((wm * 64 + mf * 16) * GP + kd * 8) * 4) + lmA);
            uint32_t bf[2][4];
#pragma unroll
            for (int p = 0; p < 2; p++)
                LDSM4(bf[p][0], bf[p][1], bf[p][2], bf[p][3],
                      Bb + (uint32_t)(((wn * 32 + p * 16) * GP + kd * 8) * 4) + lmB);
#pragma unroll
            for (int mf = 0; mf < 4; mf++)
#pragma unroll
                for (int p = 0; p < 2; p++) {
                    uint32_t f0[2] = {bf[p][0], bf[p][1]};
                    uint32_t f1[2] = {bf[p][2], bf[p][3]};
                    mma_f16(acc[mf][2 * p],     af[mf], f0);
                    mma_f16(acc[mf][2 * p + 1], af[mf], f1);
                }
        }
    }

#pragma unroll
    for (int mf = 0; mf < 4; mf++) {
#pragma unroll
        for (int nf = 0; nf < 4; nf++) {
            const int col = n0 + wn * 32 + nf * 8 + qt * 2;
#pragma unroll
            for (int jr = 0; jr < 2; jr++) {
                const int m = m0 + wm * 64 + mf * 16 + quad + 8 * jr;
                float v0 = acc[mf][nf][2 * jr];
                float v1 = acc[mf][nf][2 * jr + 1];
                if (mode == 0) {
                    v0 += bias[col]; v1 += bias[col + 1];
                    *(float2*)((float*)C + (size_t)m * D_MODEL + col) = make_float2(v0, v1);
                } else if (mode == 1) {
                    v0 = (v0 + bias[col]) * oscale;
                    v1 = (v1 + bias[col + 1]) * oscale;
                    const int bb = m >> 11, sq = m & (SEQ - 1);
                    const int h = col >> 6, pairp = (col & 63) >> 1;
                    ((uint32_t*)C)[((size_t)(bb * NHEAD + h) * SEQ + sq) * (DK/2) + pairp] = pk2(v0, v1);
                } else {
                    const float bv = bias[m];
                    v0 += bv; v1 += bv;
                    const int bb = col >> 11, sq = col & (SEQ - 1);
                    const int h = m >> 6, dk = m & (DK - 1);
                    ((uint32_t*)C)[((size_t)(bb * NHEAD + h) * DK + dk) * (SEQ/2) + (sq >> 1)] = pk2(v0, v1);
                }
            }
        }
    }
}

#define QSCALE (0.125f * 1.4426950408889634f)

__global__ void __launch_bounds__(256, 2) gemm_qkv(
    uint32_t* outQ, uint32_t* outK, uint32_t* outVt,
    const float* __restrict__ bq, const float* __restrict__ bk, const float* __restrict__ bv)
{
    extern __shared__ uint32_t su[];
    const int z = blockIdx.z;
    if (z == 0)      gemm_body(h_q,  h_wq, bq, outQ,  1, QSCALE, blockIdx.y * 128, blockIdx.x * 128, su);
    else if (z == 1) gemm_body(h_k,  h_wk, bk, outK,  1, 1.0f,   blockIdx.y * 128, blockIdx.x * 128, su);
    else             gemm_body(h_wv, h_v,  bv, outVt, 2, 1.0f,   blockIdx.x * 128, blockIdx.y * 128, su);
}

__global__ void __launch_bounds__(256, 2) gemm_out(
    const float* __restrict__ bias, float* __restrict__ C)
{
    extern __shared__ uint32_t su[];
    gemm_body((const __half*)g_AOh, h_wo, bias, C, 0, 1.0f, blockIdx.y * 128, blockIdx.x * 128, su);
}

// ---------------------------------------------------------------------------
// Flash attention (R15, proven): fp16 mma, register P, ldmatrix B-frags,
// mask fast-path, skip-rescale, 3-stage cp.async, exp2-domain softmax.
// ---------------------------------------------------------------------------
#define QP 36
#define KP 36
#define VP 36
#define ANST 3
#define ATTN_SMEM ((128*QP + ANST*64*KP + ANST*64*VP) * 4)   // 73728 B

__device__ __forceinline__ void attn_issue(
    const uint32_t* __restrict__ Kg, const uint32_t* __restrict__ Vg,
    int kt, uint32_t kbase, uint32_t vbase)
{
    const int tid = threadIdx.x;
#pragma unroll
    for (int t = 0; t < 2; t++) {
        int f   = tid + t * 256;
        int row = f >> 3;
        int seg = f & 7;
        CP16(kbase + (row * KP + seg * 4) * 4,
             Kg + (size_t)(kt + row) * (DK/2) + seg * 4);
        CP16(vbase + (row * VP + seg * 4) * 4,
             Vg + (size_t)row * (SEQ/2) + (kt >> 1) + seg * 4);
    }
}

__global__ void __launch_bounds__(256, 2) attn_kernel()
{
    extern __shared__ uint32_t su[];
    uint32_t* Qp  = su;                        // [128][QP]
    uint32_t* Kp0 = Qp + 128 * QP;             // [64][KP] x3 stages
    uint32_t* Vp0 = Kp0 + ANST * 64 * KP;      // [64][VP] x3 stages
    const uint32_t kb = smem_u32(Kp0);
    const uint32_t vb = smem_u32(Vp0);

    const int tid  = threadIdx.x;
    const int w    = tid >> 5;
    const int lane = tid & 31;
    const int quad = lane >> 2;
    const int qt   = lane & 3;
    const int bh   = blockIdx.y;
    const int b    = bh >> 4;
    const int h    = bh & 15;
    const int q0   = blockIdx.x * 128;
    const int r0   = w * 16 + quad;

    const int lmj = lane >> 3, lmr = lane & 7;
    const uint32_t lm_off = (uint32_t)(((lmj >> 1) * 8 + lmr) * KP + (lmj & 1) * 4) * 4;

    const uint32_t* Qg = g_Qh  + ((size_t)bh * SEQ + q0) * (DK/2);
    const uint32_t* Kg = g_Kh  + (size_t)bh * SEQ * (DK/2);
    const uint32_t* Vg = g_Vth + (size_t)bh * DK * (SEQ/2);

    attn_issue(Kg, Vg, 0,  kb,                vb);
    CP_COMMIT();
    attn_issue(Kg, Vg, 64, kb + 64 * KP * 4,  vb + 64 * VP * 4);
    CP_COMMIT();

#pragma unroll
    for (int t = 0; t < 8; t++) {
        int f = tid + t * 256, row = f >> 4, c2 = (f & 15) * 2;
        *(uint2*)(Qp + row * QP + c2) = *(const uint2*)(Qg + (size_t)row * (DK/2) + c2);
    }
    __syncthreads();

    uint32_t qa[4][4];
#pragma unroll
    for (int kd = 0; kd < 4; kd++) {
        const uint32_t* ap = Qp + r0 * QP + kd * 8 + qt;
        qa[kd][0] = ap[0];
        qa[kd][1] = ap[8 * QP];
        qa[kd][2] = ap[4];
        qa[kd][3] = ap[8 * QP + 4];
    }

    float oacc[8][4];
#pragma unroll
    for (int nf = 0; nf < 8; nf++)
#pragma unroll
        for (int j = 0; j < 4; j++) oacc[nf][j] = 0.f;
    float mi[2] = {-INFINITY, -INFINITY};
    float li[2] = {0.f, 0.f};

    for (int t = 0; t < 32; t++) {
        const int st = t % ANST;
        const int kt = t * 64;

        CP_WAIT(1);
        __syncthreads();
        if (t + 2 < 32) {
            const int si = (t + 2) % ANST;
            attn_issue(Kg, Vg, kt + 128, kb + si * 64 * KP * 4,
                                          vb + si * 64 * VP * 4);
        }
        CP_COMMIT();

        const uint32_t kaddr = kb + st * 64 * KP * 4 + lm_off;
        const uint32_t vaddr = vb + st * 64 * VP * 4 + lm_off;

        float sacc[8][4];
#pragma unroll
        for (int nf = 0; nf < 8; nf++)
#pragma unroll
            for (int j = 0; j < 4; j++) sacc[nf][j] = 0.f;

#pragma unroll
        for (int kd = 0; kd < 4; kd++) {
#pragma unroll
            for (int p = 0; p < 4; p++) {
                uint32_t b0, b1, b2, b3;
                LDSM4(b0, b1, b2, b3, kaddr + (uint32_t)(p * 16 * KP + kd * 8) * 4);
                uint32_t f0[2] = {b0, b1};
                uint32_t f1[2] = {b2, b3};
                mma_f16(sacc[2 * p],     qa[kd], f0);
                mma_f16(sacc[2 * p + 1], qa[kd], f1);
            }
        }

        uint32_t pe[8][2];
#pragma unroll
        for (int r = 0; r < 2; r++) {
            const int qr = q0 + r0 + r * 8;
            uint2 mw = *(const uint2*)(g_Mb + ((size_t)b * SEQ + qr) * (SEQ/32) + (kt >> 5));
            float p[16];
            float mx = -INFINITY;
            if ((mw.x & mw.y) == 0xFFFFFFFFu) {
#pragma unroll
                for (int nf = 0; nf < 8; nf++) {
                    float s0 = sacc[nf][2 * r];
                    float s1 = sacc[nf][2 * r + 1];
                    p[2 * nf]     = s0;
                    p[2 * nf + 1] = s1;
                    mx = fmaxf(mx, fmaxf(s0, s1));
                }
            } else {
#pragma unroll
                for (int nf = 0; nf < 8; nf++) {
                    const uint32_t wsel = (nf < 4) ? mw.x : mw.y;
                    const int bit = (nf * 8 + qt * 2) & 31;
                    float s0 = ((wsel >> bit) & 1u)       ? sacc[nf][2 * r]     : -INFINITY;
                    float s1 = ((wsel >> (bit + 1)) & 1u) ? sacc[nf][2 * r + 1] : -INFINITY;
                    p[2 * nf]     = s0;
                    p[2 * nf + 1] = s1;
                    mx = fmaxf(mx, fmaxf(s0, s1));
                }
            }
            mx = fmaxf(mx, __shfl_xor_sync(0xffffffffu, mx, 1));
            mx = fmaxf(mx, __shfl_xor_sync(0xffffffffu, mx, 2));
            const float mnew = fmaxf(mi[r], mx);
            const bool  chg  = (mnew != mi[r]);
            const float al   = chg ? exp2f(mi[r] - mnew) : 1.0f;
            float rs = 0.f;
#pragma unroll
            for (int nf = 0; nf < 8; nf++) {
                float e0 = exp2f(p[2 * nf]     - mnew);
                float e1 = exp2f(p[2 * nf + 1] - mnew);
                rs += e0 + e1;
                pe[nf][r] = pk2(e0, e1);
            }
            rs += __shfl_xor_sync(0xffffffffu, rs, 1);
            rs += __shfl_xor_sync(0xffffffffu, rs, 2);
            li[r] = li[r] * al + rs;
            mi[r] = mnew;
            if (chg) {
#pragma unroll
                for (int nf = 0; nf < 8; nf++) {
                    oacc[nf][2 * r]     *= al;
                    oacc[nf][2 * r + 1] *= al;
                }
            }
        }

#pragma unroll
        for (int kk = 0; kk < 4; kk++) {
            uint32_t a[4];
            a[0] = pe[2 * kk][0];
            a[1] = pe[2 * kk][1];
            a[2] = pe[2 * kk + 1][0];
            a[3] = pe[2 * kk + 1][1];
#pragma unroll
            for (int p = 0; p < 4; p++) {
                uint32_t b0, b1, b2, b3;
                LDSM4(b0, b1, b2, b3, vaddr + (uint32_t)(p * 16 * VP + kk * 8) * 4);
                uint32_t f0[2] = {b0, b1};
                uint32_t f1[2] = {b2, b3};
                mma_f16(oacc[2 * p],     a, f0);
                mma_f16(oacc[2 * p + 1], a, f1);
            }
        }
    }

#pragma unroll
    for (int r = 0; r < 2; r++) {
        const int qr = q0 + r0 + 8 * r;
        const float inv = 1.f / li[r];
        uint32_t* dst = g_AOh + (size_t)(b * SEQ + qr) * (D_MODEL/2) + h * (DK/2);
#pragma unroll
        for (int nf = 0; nf < 8; nf++)
            dst[nf * 4 + qt] = pk2(oacc[nf][2 * r] * inv, oacc[nf][2 * r + 1] * inv);
    }
}

// ---------------------------------------------------------------------------
extern "C" void kernel_launch(void* const* d_in, const int* in_sizes, int n_in,
                              void* d_out, int out_size)
{
    const float* q   = (const float*)d_in[0];
    const float* k   = (const float*)d_in[1];
    const float* v   = (const float*)d_in[2];
    const int*   msk = (const int*)  d_in[3];
    const float* b_q = (const float*)d_in[5];
    const float* b_k = (const float*)d_in[7];
    const float* b_v = (const float*)d_in[9];
    const float* b_o = (const float*)d_in[11];
    float* out = (float*)d_out;

    void *hq, *hk, *hv, *hwq, *hwk, *hwv, *hwo, *gQ, *gK, *gVt, *gMb;
    cudaGetSymbolAddress(&hq,  h_q);
    cudaGetSymbolAddress(&hk,  h_k);
    cudaGetSymbolAddress(&hv,  h_v);
    cudaGetSymbolAddress(&hwq, h_wq);
    cudaGetSymbolAddress(&hwk, h_wk);
    cudaGetSymbolAddress(&hwv, h_wv);
    cudaGetSymbolAddress(&hwo, h_wo);
    cudaGetSymbolAddress(&gQ,  g_Qh);
    cudaGetSymbolAddress(&gK,  g_Kh);
    cudaGetSymbolAddress(&gVt, g_Vth);
    cudaGetSymbolAddress(&gMb, g_Mb);

    cudaFuncSetAttribute(gemm_qkv,    cudaFuncAttributeMaxDynamicSharedMemorySize, GEMM_SMEM);
    cudaFuncSetAttribute(gemm_out,    cudaFuncAttributeMaxDynamicSharedMemorySize, GEMM_SMEM);
    cudaFuncSetAttribute(attn_kernel, cudaFuncAttributeMaxDynamicSharedMemorySize, ATTN_SMEM);

    dim3 pgrid(ACT4 / 256, 1, 7);
    prepass_half<<<pgrid, 256>>>(
        (const float4*)q, (const float4*)k, (const float4*)v,
        (const float4*)d_in[4], (const float4*)d_in[6],
        (const float4*)d_in[8], (const float4*)d_in[10],
        (uint2*)hq, (uint2*)hk, (uint2*)hv,
        (uint2*)hwq, (uint2*)hwk, (uint2*)hwv, (uint2*)hwo);
    mask_bits<<<BATCH * SEQ * (SEQ/32) / 8, 256>>>(msk, (uint32_t*)gMb);

    dim3 qkvgrid(8, 32, 3);
    gemm_qkv<<<qkvgrid, 256, GEMM_SMEM>>>((uint32_t*)gQ, (uint32_t*)gK, (uint32_t*)gVt,
                                          b_q, b_k, b_v);

    dim3 agrid(SEQ / 128, BATCH * NHEAD);
    attn_kernel<<<agrid, 256, ATTN_SMEM>>>();

    dim3 ogrid(8, 32);
    gemm_out<<<ogrid, 256, GEMM_SMEM>>>(b_o, out);
}